// round 12
// baseline (speedup 1.0000x reference)
#include <cuda_runtime.h>
#include <cuda_bf16.h>
#include <cstdint>

#define Bb  2
#define Ss  2048
#define Dd  1024
#define Hh  16
#define DKk 64
#define Mm  (Bb*Ss)

// ---------------- scratch (allocation-free: device globals) ----------------
__device__ __nv_bfloat16 g_A0hi[(size_t)Mm*Dd], g_A0lo[(size_t)Mm*Dd];
__device__ __nv_bfloat16 g_A1hi[(size_t)Mm*Dd], g_A1lo[(size_t)Mm*Dd];
__device__ __nv_bfloat16 g_A2hi[(size_t)Mm*Dd], g_A2lo[(size_t)Mm*Dd];
__device__ __nv_bfloat16 g_W0hi[(size_t)Dd*Dd], g_W0lo[(size_t)Dd*Dd];
__device__ __nv_bfloat16 g_W1hi[(size_t)Dd*Dd], g_W1lo[(size_t)Dd*Dd];
__device__ __nv_bfloat16 g_W2hi[(size_t)Dd*Dd], g_W2lo[(size_t)Dd*Dd];
__device__ __nv_bfloat16 g_W3hi[(size_t)Dd*Dd], g_W3lo[(size_t)Dd*Dd];
__device__ __nv_bfloat16 g_Qhi[(size_t)Bb*Hh*Ss*DKk], g_Qlo[(size_t)Bb*Hh*Ss*DKk];
__device__ __nv_bfloat16 g_Khi[(size_t)Bb*Hh*Ss*DKk], g_Klo[(size_t)Bb*Hh*Ss*DKk];
__device__ __nv_bfloat16 g_Vthi[(size_t)Bb*Hh*DKk*Ss], g_Vtlo[(size_t)Bb*Hh*DKk*Ss];
__device__ __nv_bfloat16 g_Xhi[(size_t)Mm*Dd], g_Xlo[(size_t)Mm*Dd];

// ---------------- helpers (arch-portable PTX) --------
__device__ __forceinline__ uint32_t smem_u32(const void* p) {
    uint32_t a;
    asm("{ .reg .u64 t; cvta.to.shared.u64 t, %1; cvt.u32.u64 %0, t; }"
        : "=r"(a) : "l"(p));
    return a;
}
__device__ __forceinline__ void ldsm4(uint32_t a, uint32_t& r0, uint32_t& r1,
                                      uint32_t& r2, uint32_t& r3) {
    asm volatile("ldmatrix.sync.aligned.m8n8.x4.shared.b16 {%0,%1,%2,%3}, [%4];"
                 : "=r"(r0), "=r"(r1), "=r"(r2), "=r"(r3) : "r"(a));
}
__device__ __forceinline__ void mma16816(float* c, uint32_t a0, uint32_t a1,
                                         uint32_t a2, uint32_t a3,
                                         uint32_t b0, uint32_t b1) {
    asm volatile(
        "mma.sync.aligned.m16n8k16.row.col.f32.bf16.bf16.f32 "
        "{%0,%1,%2,%3}, {%4,%5,%6,%7}, {%8,%9}, {%0,%1,%2,%3};"
        : "+f"(c[0]), "+f"(c[1]), "+f"(c[2]), "+f"(c[3])
        : "r"(a0), "r"(a1), "r"(a2), "r"(a3), "r"(b0), "r"(b1));
}
__device__ __forceinline__ uint32_t packbf(float lo, float hi) {
    uint32_t r;
    asm("cvt.rn.bf16x2.f32 %0, %1, %2;" : "=r"(r) : "f"(hi), "f"(lo));
    return r;
}
__device__ __forceinline__ float bflo_f(uint32_t p) { return __uint_as_float(p << 16); }
__device__ __forceinline__ float bfhi_f(uint32_t p) { return __uint_as_float(p & 0xffff0000u); }
__device__ __forceinline__ float ex2f(float x) {
    float r;
    asm("ex2.approx.f32 %0, %1;" : "=f"(r) : "f"(x));
    return r;
}

__device__ __forceinline__ void cpasync16(uint32_t saddr, const void* g) {
    asm volatile("cp.async.ca.shared.global [%0], [%1], 16;"
                 :: "r"(saddr), "l"(g) : "memory");
}
#define CP_COMMIT() asm volatile("cp.async.commit_group;" ::: "memory")
#define CP_WAIT0()  asm volatile("cp.async.wait_group 0;" ::: "memory")

// ---------------------------------------------------------------------------
// merged fp32 -> bf16 hi/lo splits for q,k,v activations
// ---------------------------------------------------------------------------
__global__ __launch_bounds__(256) void conv_act_all(
    const float* __restrict__ q, const float* __restrict__ k,
    const float* __restrict__ v)
{
    const float* src = (blockIdx.y == 0) ? q : (blockIdx.y == 1) ? k : v;
    __nv_bfloat16* hi = (blockIdx.y == 0) ? g_A0hi : (blockIdx.y == 1) ? g_A1hi : g_A2hi;
    __nv_bfloat16* lo = (blockIdx.y == 0) ? g_A0lo : (blockIdx.y == 1) ? g_A1lo : g_A2lo;
    int i = blockIdx.x * blockDim.x + threadIdx.x;
    float4 vv = ((const float4*)src)[i];
    uint32_t h0 = packbf(vv.x, vv.y), h1 = packbf(vv.z, vv.w);
    ((uint32_t*)hi)[i * 2 + 0] = h0;
    ((uint32_t*)hi)[i * 2 + 1] = h1;
    ((uint32_t*)lo)[i * 2 + 0] = packbf(vv.x - bflo_f(h0), vv.y - bfhi_f(h0));
    ((uint32_t*)lo)[i * 2 + 1] = packbf(vv.z - bflo_f(h1), vv.w - bfhi_f(h1));
}

// ---------------------------------------------------------------------------
// merged weight transpose + split: W[K,N] -> WT[N,K] hi/lo, 4 weights
// ---------------------------------------------------------------------------
__global__ __launch_bounds__(256) void conv_wt_all(
    const float* __restrict__ w0, const float* __restrict__ w1,
    const float* __restrict__ w2, const float* __restrict__ w3)
{
    __shared__ float ts[32][33];
    const int z = blockIdx.z;
    const float* W = (z == 0) ? w0 : (z == 1) ? w1 : (z == 2) ? w2 : w3;
    __nv_bfloat16* hiT = (z == 0) ? g_W0hi : (z == 1) ? g_W1hi : (z == 2) ? g_W2hi : g_W3hi;
    __nv_bfloat16* loT = (z == 0) ? g_W0lo : (z == 1) ? g_W1lo : (z == 2) ? g_W2lo : g_W3lo;
    int tx = threadIdx.x, ty = threadIdx.y;          // 32 x 8
    int bn = blockIdx.x * 32, bk = blockIdx.y * 32;
    #pragma unroll
    for (int r = 0; r < 4; r++)
        ts[ty + r * 8][tx] = W[(size_t)(bk + ty + r * 8) * Dd + bn + tx];
    __syncthreads();
    #pragma unroll
    for (int r = 0; r < 4; r++) {
        float x = ts[tx][ty + r * 8];
        __nv_bfloat16 h = __float2bfloat16(x);
        size_t o = (size_t)(bn + ty + r * 8) * Dd + bk + tx;
        hiT[o] = h;
        loT[o] = __float2bfloat16(x - __bfloat162float(h));
    }
}

// ---------------------------------------------------------------------------
// HMMA bf16x3 GEMM body: cp.async double-buffered, 2 CTAs/SM. (R10 config)
// ---------------------------------------------------------------------------
#define KCH   32
#define NCHUNK (Dd / KCH)          // 32
#define SROW  40                   // padded halves per row
#define ABYTES (128 * SROW * 2)    // 10240 B per array
#define BUFB  (4 * ABYTES)         // 40960 B per stage
#define GSMEM (2 * BUFB)           // 81920 B

__device__ __forceinline__ void hgemm_body(
    const __nv_bfloat16* __restrict__ Ahi, const __nv_bfloat16* __restrict__ Alo,
    const __nv_bfloat16* __restrict__ Whi, const __nv_bfloat16* __restrict__ Wlo,
    const float* __restrict__ bias, float* __restrict__ Cf,
    __nv_bfloat16* __restrict__ Chi, __nv_bfloat16* __restrict__ Clo,
    int mode, __nv_bfloat16* sm)
{
    const int tid  = threadIdx.x;
    const int wid  = tid >> 5, lane = tid & 31;
    const int bm   = blockIdx.y * 128, bn = blockIdx.x * 128;
    const int wm   = wid & 1, wn = wid >> 1;

    float c[4][4][4];
    #pragma unroll
    for (int i = 0; i < 4; i++)
        #pragma unroll
        for (int j = 0; j < 4; j++)
            #pragma unroll
            for (int r = 0; r < 4; r++) c[i][j][r] = 0.f;

    const int r0 = tid >> 2,         q0 = (tid & 3) * 8;
    const int r1 = (tid + 256) >> 2, q1 = ((tid + 256) & 3) * 8;
    const uint32_t sb = smem_u32(sm);

    #define ISSUE_CHUNK(cc, base) do {                                          \
        const int k0_ = (cc) * KCH;                                             \
        cpasync16((base) + (uint32_t)((0 * 128 * SROW + r0 * SROW + q0) * 2),   \
                  &Ahi[(size_t)(bm + r0) * Dd + k0_ + q0]);                     \
        cpasync16((base) + (uint32_t)((0 * 128 * SROW + r1 * SROW + q1) * 2),   \
                  &Ahi[(size_t)(bm + r1) * Dd + k0_ + q1]);                     \
        cpasync16((base) + (uint32_t)((1 * 128 * SROW + r0 * SROW + q0) * 2),   \
                  &Alo[(size_t)(bm + r0) * Dd + k0_ + q0]);                     \
        cpasync16((base) + (uint32_t)((1 * 128 * SROW + r1 * SROW + q1) * 2),   \
                  &Alo[(size_t)(bm + r1) * Dd + k0_ + q1]);                     \
        cpasync16((base) + (uint32_t)((2 * 128 * SROW + r0 * SROW + q0) * 2),   \
                  &Whi[(size_t)(bn + r0) * Dd + k0_ + q0]);                     \
        cpasync16((base) + (uint32_t)((2 * 128 * SROW + r1 * SROW + q1) * 2),   \
                  &Whi[(size_t)(bn + r1) * Dd + k0_ + q1]);                     \
        cpasync16((base) + (uint32_t)((3 * 128 * SROW + r0 * SROW + q0) * 2),   \
                  &Wlo[(size_t)(bn + r0) * Dd + k0_ + q0]);                     \
        cpasync16((base) + (uint32_t)((3 * 128 * SROW + r1 * SROW + q1) * 2),   \
                  &Wlo[(size_t)(bn + r1) * Dd + k0_ + q1]);                     \
        CP_COMMIT();                                                            \
    } while (0)

    const uint32_t aoff =
        (uint32_t)(((wm * 64 + (lane & 15)) * SROW + (lane >> 4) * 8) * 2);
    const uint32_t boff4 =
        (uint32_t)(((wn * 32 + (lane >> 4) * 8 + (lane & 7)) * SROW
                    + ((lane >> 3) & 1) * 8) * 2);

    ISSUE_CHUNK(0, sb);

    for (int cc = 0; cc < NCHUNK; cc++) {
        CP_WAIT0();
        __syncthreads();
        if (cc + 1 < NCHUNK)
            ISSUE_CHUNK(cc + 1, sb + (uint32_t)((cc + 1) & 1) * BUFB);

        const uint32_t bufb = sb + (uint32_t)(cc & 1) * BUFB;
        #pragma unroll
        for (int ks = 0; ks < 2; ks++) {
            uint32_t ah[4][4], bh[4][2], bl[4][2];
            #pragma unroll
            for (int mi = 0; mi < 4; mi++)
                ldsm4(bufb + aoff + mi * (16 * SROW * 2) + ks * 32,
                      ah[mi][0], ah[mi][1], ah[mi][2], ah[mi][3]);
            #pragma unroll
            for (int nb = 0; nb < 2; nb++)
                ldsm4(bufb + 2u * ABYTES + boff4 + nb * (16 * SROW * 2) + ks * 32,
                      bh[2 * nb][0], bh[2 * nb][1], bh[2 * nb + 1][0], bh[2 * nb + 1][1]);
            #pragma unroll
            for (int nb = 0; nb < 2; nb++)
                ldsm4(bufb + 3u * ABYTES + boff4 + nb * (16 * SROW * 2) + ks * 32,
                      bl[2 * nb][0], bl[2 * nb][1], bl[2 * nb + 1][0], bl[2 * nb + 1][1]);
            #pragma unroll
            for (int mi = 0; mi < 4; mi++)
                #pragma unroll
                for (int ni = 0; ni < 4; ni++)
                    mma16816(c[mi][ni], ah[mi][0], ah[mi][1], ah[mi][2], ah[mi][3],
                             bh[ni][0], bh[ni][1]);
            #pragma unroll
            for (int mi = 0; mi < 4; mi++)
                #pragma unroll
                for (int ni = 0; ni < 4; ni++)
                    mma16816(c[mi][ni], ah[mi][0], ah[mi][1], ah[mi][2], ah[mi][3],
                             bl[ni][0], bl[ni][1]);
            #pragma unroll
            for (int mi = 0; mi < 4; mi++)
                ldsm4(bufb + (uint32_t)ABYTES + aoff + mi * (16 * SROW * 2) + ks * 32,
                      ah[mi][0], ah[mi][1], ah[mi][2], ah[mi][3]);
            #pragma unroll
            for (int mi = 0; mi < 4; mi++)
                #pragma unroll
                for (int ni = 0; ni < 4; ni++)
                    mma16816(c[mi][ni], ah[mi][0], ah[mi][1], ah[mi][2], ah[mi][3],
                             bh[ni][0], bh[ni][1]);
        }
    }

    // ---- epilogue ----
    const int mrow0 = bm + wm * 64 + (lane >> 2);
    const int ncol0 = bn + wn * 32 + (lane & 3) * 2;
    #pragma unroll
    for (int mi = 0; mi < 4; mi++) {
        #pragma unroll
        for (int h2 = 0; h2 < 2; h2++) {
            const int m = mrow0 + mi * 16 + h2 * 8;
            const int b = m >> 11, s = m & 2047;
            #pragma unroll
            for (int ni = 0; ni < 4; ni++) {
                const int n = ncol0 + ni * 8;
                float v0 = c[mi][ni][h2 * 2 + 0] + bias[n];
                float v1 = c[mi][ni][h2 * 2 + 1] + bias[n + 1];
                if (mode == 0) {
                    float2 v; v.x = v0; v.y = v1;
                    *(float2*)&Cf[(size_t)m * Dd + n] = v;
                } else {
                    const int h = n >> 6, dk = n & 63;
                    uint32_t hp = packbf(v0, v1);
                    uint32_t lp = packbf(v0 - bflo_f(hp), v1 - bfhi_f(hp));
                    if (mode == 1) {
                        size_t o = (((size_t)(b * Hh + h)) * Ss + s) * DKk + dk;
                        *(uint32_t*)&Chi[o] = hp;
                        *(uint32_t*)&Clo[o] = lp;
                    } else {
                        size_t o = (((size_t)(b * Hh + h)) * DKk + dk) * Ss + s;
                        Chi[o]      = __ushort_as_bfloat16((uint16_t)(hp & 0xffff));
                        Chi[o + Ss] = __ushort_as_bfloat16((uint16_t)(hp >> 16));
                        Clo[o]      = __ushort_as_bfloat16((uint16_t)(lp & 0xffff));
                        Clo[o + Ss] = __ushort_as_bfloat16((uint16_t)(lp >> 16));
                    }
                }
            }
        }
    }
    #undef ISSUE_CHUNK
}

// batched QKV projections: blockIdx.z selects {Q, K, V}
__global__ __launch_bounds__(256, 2) void hgemm_qkv(
    const float* __restrict__ b_q, const float* __restrict__ b_k,
    const float* __restrict__ b_v)
{
    extern __shared__ __nv_bfloat16 smg[];
    const int z = blockIdx.z;
    if (z == 0)
        hgemm_body(g_A0hi, g_A0lo, g_W0hi, g_W0lo, b_q, nullptr, g_Qhi, g_Qlo, 1, smg);
    else if (z == 1)
        hgemm_body(g_A1hi, g_A1lo, g_W1hi, g_W1lo, b_k, nullptr, g_Khi, g_Klo, 1, smg);
    else
        hgemm_body(g_A2hi, g_A2lo, g_W2hi, g_W2lo, b_v, nullptr, g_Vthi, g_Vtlo, 2, smg);
}

__global__ __launch_bounds__(256, 2) void hgemm_out(
    const float* __restrict__ b_o, float* __restrict__ out)
{
    extern __shared__ __nv_bfloat16 smg[];
    hgemm_body(g_Xhi, g_Xlo, g_W3hi, g_W3lo, b_o, out, nullptr, nullptr, 0, smg);
}

// ---------------------------------------------------------------------------
// HMMA flash attention, bf16x3, causal, cp.async double-buffered KV.
// CTA: 128 query rows of one (b,h); 4 warps x 32 rows (2 m-tiles each).
// KV tiles of 64 keys. Every K/V fragment feeds 2 MMAs (A-reuse = 2).
// Q-lo reloaded from smem per kk; P-frags exp/packed JIT in PV loop.
// ---------------------------------------------------------------------------
#define APAD 72
#define QROWS 128
#define Q_TILE (QROWS * APAD)          // 9216 halves
#define KV_TILE (64 * APAD)            // 4608 halves
#define STAGE_H (4 * KV_TILE)          // KH,KL,VH,VL per stage
#define OFF_ST (2 * Q_TILE)
#define ATTN_SMEM ((2 * Q_TILE + 2 * STAGE_H) * 2)   // 110592 B
#define SCL2 0.18033688f               // 0.125 * log2(e)

__global__ __launch_bounds__(128, 1) void attn_mma_kernel(
    const __nv_bfloat16* __restrict__ Qhi, const __nv_bfloat16* __restrict__ Qlo,
    const __nv_bfloat16* __restrict__ Khi, const __nv_bfloat16* __restrict__ Klo,
    const __nv_bfloat16* __restrict__ Vthi, const __nv_bfloat16* __restrict__ Vtlo,
    __nv_bfloat16* __restrict__ Xhi, __nv_bfloat16* __restrict__ Xlo)
{
    extern __shared__ __nv_bfloat16 smA[];
    const int tid  = threadIdx.x;
    const int w    = tid >> 5, lane = tid & 31;
    const int bh   = blockIdx.y;
    const int iq   = gridDim.x - 1 - blockIdx.x;   // long CTAs first
    const size_t baseQK = (size_t)bh * Ss * DKk;
    const size_t baseV  = (size_t)bh * DKk * Ss;
    const uint32_t sb = smem_u32(smA);

    #define ISSUE_KV(j, stg) do {                                               \
        const __nv_bfloat16* Kh_g = Khi + baseQK + (size_t)(j) * 64 * DKk;      \
        const __nv_bfloat16* Kl_g = Klo + baseQK + (size_t)(j) * 64 * DKk;      \
        const __nv_bfloat16* Vh_g = Vthi + baseV + (size_t)(j) * 64;            \
        const __nv_bfloat16* Vl_g = Vtlo + baseV + (size_t)(j) * 64;            \
        const uint32_t st = sb + (uint32_t)((OFF_ST + (stg) * STAGE_H) * 2);    \
        _Pragma("unroll")                                                       \
        for (int t = 0; t < 4; t++) {                                           \
            int idx = tid + t * 128;                                            \
            int row = idx >> 3, cu = (idx & 7) * 8;                             \
            cpasync16(st + (uint32_t)((0 * KV_TILE + row * APAD + cu) * 2),     \
                      &Kh_g[row * DKk + cu]);                                   \
            cpasync16(st + (uint32_t)((1 * KV_TILE + row * APAD + cu) * 2),     \
                      &Kl_g[row * DKk + cu]);                                   \
            cpasync16(st + (uint32_t)((2 * KV_TILE + row * APAD + cu) * 2),     \
                      &Vh_g[(size_t)row * Ss + cu]);                            \
            cpasync16(st + (uint32_t)((3 * KV_TILE + row * APAD + cu) * 2),     \
                      &Vl_g[(size_t)row * Ss + cu]);                            \
        }                                                                       \
        CP_COMMIT();                                                            \
    } while (0)

    // ---- load Q tile (128x64 hi/lo) + prefetch KV tile 0 ----
    {
        const __nv_bfloat16* Qh_g = Qhi + baseQK + (size_t)iq * QROWS * DKk;
        const __nv_bfloat16* Ql_g = Qlo + baseQK + (size_t)iq * QROWS * DKk;
        #pragma unroll
        for (int t = 0; t < 8; t++) {
            int idx = tid + t * 128;           // 0..1023
            int row = idx >> 3, cu = (idx & 7) * 8;
            *(uint4*)&smA[0 * Q_TILE + row * APAD + cu] = *(const uint4*)&Qh_g[row * DKk + cu];
            *(uint4*)&smA[1 * Q_TILE + row * APAD + cu] = *(const uint4*)&Ql_g[row * DKk + cu];
        }
    }
    ISSUE_KV(0, 0);
    __syncthreads();

    // A-frag addresses per m-tile (warp rows w*32 + mt*16 + ...)
    uint32_t a_off[2];
    #pragma unroll
    for (int mt = 0; mt < 2; mt++)
        a_off[mt] = (uint32_t)(((w * 32 + mt * 16 + (lane & 15)) * APAD
                                + (lane >> 4) * 8) * 2);
    const uint32_t b_off = (uint32_t)((((lane & 15)) * APAD + (lane >> 4) * 8) * 2);

    // Q-hi fragments held in registers; Q-lo reloaded per kk
    uint32_t qh[2][4][4];
    #pragma unroll
    for (int mt = 0; mt < 2; mt++)
        #pragma unroll
        for (int kk = 0; kk < 4; kk++)
            ldsm4(sb + a_off[mt] + kk * 32,
                  qh[mt][kk][0], qh[mt][kk][1], qh[mt][kk][2], qh[mt][kk][3]);

    float o[2][8][4];
    #pragma unroll
    for (int mt = 0; mt < 2; mt++)
        #pragma unroll
        for (int i = 0; i < 8; i++)
            #pragma unroll
            for (int r = 0; r < 4; r++) o[mt][i][r] = 0.f;
    float mrow[2][2], lrow[2][2];
    #pragma unroll
    for (int mt = 0; mt < 2; mt++) {
        mrow[mt][0] = -1e30f; mrow[mt][1] = -1e30f;
        lrow[mt][0] = 0.f;    lrow[mt][1] = 0.f;
    }

    const int jmax = 2 * iq + 1;
    for (int j = 0; j <= jmax; j++) {
        CP_WAIT0();
        __syncthreads();
        if (j < jmax) ISSUE_KV(j + 1, (j + 1) & 1);

        const uint32_t stb = sb + (uint32_t)((OFF_ST + (j & 1) * STAGE_H) * 2);

        // ---- scores S = Q K^T (3-term) ----
        float s[2][8][4];
        #pragma unroll
        for (int mt = 0; mt < 2; mt++)
            #pragma unroll
            for (int i = 0; i < 8; i++)
                #pragma unroll
                for (int r = 0; r < 4; r++) s[mt][i][r] = 0.f;

        #pragma unroll
        for (int kk = 0; kk < 4; kk++) {
            uint32_t kh[8][2], kl[8][2];
            #pragma unroll
            for (int np = 0; np < 4; np++) {
                uint32_t t0, t1, t2, t3;
                ldsm4(stb + 0 * KV_TILE * 2 + b_off + np * (16 * APAD * 2) + kk * 32,
                      t0, t1, t2, t3);
                kh[2 * np][0] = t0; kh[2 * np][1] = t2;
                kh[2 * np + 1][0] = t1; kh[2 * np + 1][1] = t3;
                ldsm4(stb + 1 * KV_TILE * 2 + b_off + np * (16 * APAD * 2) + kk * 32,
                      t0, t1, t2, t3);
                kl[2 * np][0] = t0; kl[2 * np][1] = t2;
                kl[2 * np + 1][0] = t1; kl[2 * np + 1][1] = t3;
            }
            uint32_t qlf[2][4];
            #pragma unroll
            for (int mt = 0; mt < 2; mt++)
                ldsm4(sb + (uint32_t)(Q_TILE * 2) + a_off[mt] + kk * 32,
                      qlf[mt][0], qlf[mt][1], qlf[mt][2], qlf[mt][3]);
            #pragma unroll
            for (int mt = 0; mt < 2; mt++)
                #pragma unroll
                for (int ni = 0; ni < 8; ni++)
                    mma16816(s[mt][ni], qh[mt][kk][0], qh[mt][kk][1],
                             qh[mt][kk][2], qh[mt][kk][3], kh[ni][0], kh[ni][1]);
            #pragma unroll
            for (int mt = 0; mt < 2; mt++)
                #pragma unroll
                for (int ni = 0; ni < 8; ni++)
                    mma16816(s[mt][ni], qh[mt][kk][0], qh[mt][kk][1],
                             qh[mt][kk][2], qh[mt][kk][3], kl[ni][0], kl[ni][1]);
            #pragma unroll
            for (int mt = 0; mt < 2; mt++)
                #pragma unroll
                for (int ni = 0; ni < 8; ni++)
                    mma16816(s[mt][ni], qlf[mt][0], qlf[mt][1],
                             qlf[mt][2], qlf[mt][3], kh[ni][0], kh[ni][1]);
        }

        // ---- scale into exp2 domain + causal mask ----
        #pragma unroll
        for (int mt = 0; mt < 2; mt++)
            #pragma unroll
            for (int ni = 0; ni < 8; ni++)
                #pragma unroll
                for (int r = 0; r < 4; r++) s[mt][ni][r] *= SCL2;
        if (j >= 2 * iq) {
            #pragma unroll
            for (int mt = 0; mt < 2; mt++) {
                const int rlo = iq * QROWS + w * 32 + mt * 16 + (lane >> 2);
                const int rhi = rlo + 8;
                #pragma unroll
                for (int ni = 0; ni < 8; ni++) {
                    const int c0 = j * 64 + ni * 8 + (lane & 3) * 2;
                    if (c0 > rlo)     s[mt][ni][0] = -1e30f;
                    if (c0 + 1 > rlo) s[mt][ni][1] = -1e30f;
                    if (c0 > rhi)     s[mt][ni][2] = -1e30f;
                    if (c0 + 1 > rhi) s[mt][ni][3] = -1e30f;
                }
            }
        }

        // ---- softmax part 1: max reduce + o rescale ----
        float mn[2][2], al[2][2];
        #pragma unroll
        for (int mt = 0; mt < 2; mt++) {
            float mx_lo = s[mt][0][0], mx_hi = s[mt][0][2];
            #pragma unroll
            for (int ni = 0; ni < 8; ni++) {
                mx_lo = fmaxf(mx_lo, fmaxf(s[mt][ni][0], s[mt][ni][1]));
                mx_hi = fmaxf(mx_hi, fmaxf(s[mt][ni][2], s[mt][ni][3]));
            }
            mx_lo = fmaxf(mx_lo, __shfl_xor_sync(0xffffffffu, mx_lo, 1));
            mx_lo = fmaxf(mx_lo, __shfl_xor_sync(0xffffffffu, mx_lo, 2));
            mx_hi = fmaxf(mx_hi, __shfl_xor_sync(0xffffffffu, mx_hi, 1));
            mx_hi = fmaxf(mx_hi, __shfl_xor_sync(0xffffffffu, mx_hi, 2));
            mn[mt][0] = fmaxf(mrow[mt][0], mx_lo);
            mn[mt][1] = fmaxf(mrow[mt][1], mx_hi);
            al[mt][0] = ex2f(mrow[mt][0] - mn[mt][0]);
            al[mt][1] = ex2f(mrow[mt][1] - mn[mt][1]);
            #pragma unroll
            for (int ni = 0; ni < 8; ni++) {
                o[mt][ni][0] *= al[mt][0]; o[mt][ni][1] *= al[mt][0];
                o[mt][ni][2] *= al[mt][1]; o[mt][ni][3] *= al[mt][1];
            }
        }

        // ---- PV with JIT exp/pack ----
        float sum[2][2] = {{0.f, 0.f}, {0.f, 0.f}};
        #pragma unroll
        for (int kk = 0; kk < 4; kk++) {
            uint32_t pa[2][4], qa[2][4];
            #pragma unroll
            for (int mt = 0; mt < 2; mt++)
                #pragma unroll
                for (int t = 0; t < 2; t++) {
                    const int ni = 2 * kk + t;
                    float p0 = ex2f(s[mt][ni][0] - mn[mt][0]);
                    float p1 = ex2f(s[mt][ni][1] - mn[mt][0]);
                    float p2 = ex2f(s[mt][ni][2] - mn[mt][1]);
                    float p3 = ex2f(s[mt][ni][3] - mn[mt][1]);
                    sum[mt][0] += p0 + p1; sum[mt][1] += p2 + p3;
                    uint32_t h01 = packbf(p0, p1), h23 = packbf(p2, p3);
                    pa[mt][t * 2] = h01; pa[mt][t * 2 + 1] = h23;
                    qa[mt][t * 2]     = packbf(p0 - bflo_f(h01), p1 - bfhi_f(h01));
                    qa[mt][t * 2 + 1] = packbf(p2 - bflo_f(h23), p3 - bfhi_f(h23));
                }
            uint32_t vh[8][2], vl[8][2];
            #pragma unroll
            for (int np = 0; np < 4; np++) {
                uint32_t t0, t1, t2, t3;
                ldsm4(stb + 2 * KV_TILE * 2 + b_off + np * (16 * APAD * 2) + kk * 32,
                      t0, t1, t2, t3);
                vh[2 * np][0] = t0; vh[2 * np][1] = t2;
                vh[2 * np + 1][0] = t1; vh[2 * np + 1][1] = t3;
                ldsm4(stb + 3 * KV_TILE * 2 + b_off + np * (16 * APAD * 2) + kk * 32,
                      t0, t1, t2, t3);
                vl[2 * np][0] = t0; vl[2 * np][1] = t2;
                vl[2 * np + 1][0] = t1; vl[2 * np + 1][1] = t3;
            }
            #pragma unroll
            for (int mt = 0; mt < 2; mt++)
                #pragma unroll
                for (int ni = 0; ni < 8; ni++)
                    mma16816(o[mt][ni], pa[mt][0], pa[mt][1], pa[mt][2], pa[mt][3],
                             vh[ni][0], vh[ni][1]);
            #pragma unroll
            for (int mt = 0; mt < 2; mt++)
                #pragma unroll
                for (int ni = 0; ni < 8; ni++)
                    mma16816(o[mt][ni], pa[mt][0], pa[mt][1], pa[mt][2], pa[mt][3],
                             vl[ni][0], vl[ni][1]);
            #pragma unroll
            for (int mt = 0; mt < 2; mt++)
                #pragma unroll
                for (int ni = 0; ni < 8; ni++)
                    mma16816(o[mt][ni], qa[mt][0], qa[mt][1], qa[mt][2], qa[mt][3],
                             vh[ni][0], vh[ni][1]);
        }

        // ---- softmax part 2: deferred sum reduce + l update ----
        #pragma unroll
        for (int mt = 0; mt < 2; mt++) {
            float s0 = sum[mt][0], s1 = sum[mt][1];
            s0 += __shfl_xor_sync(0xffffffffu, s0, 1);
            s0 += __shfl_xor_sync(0xffffffffu, s0, 2);
            s1 += __shfl_xor_sync(0xffffffffu, s1, 1);
            s1 += __shfl_xor_sync(0xffffffffu, s1, 2);
            lrow[mt][0] = lrow[mt][0] * al[mt][0] + s0;
            lrow[mt][1] = lrow[mt][1] * al[mt][1] + s1;
            mrow[mt][0] = mn[mt][0];
            mrow[mt][1] = mn[mt][1];
        }
    }

    // ---- epilogue: X[b, s, h*64+dk] as bf16 hi/lo ----
    const int b = bh >> 4, h = bh & 15;
    #pragma unroll
    for (int mt = 0; mt < 2; mt++) {
        const float inv_lo = 1.f / lrow[mt][0], inv_hi = 1.f / lrow[mt][1];
        const int s_lo = iq * QROWS + w * 32 + mt * 16 + (lane >> 2);
        const int s_hi = s_lo + 8;
        #pragma unroll
        for (int ni = 0; ni < 8; ni++) {
            const int dk = ni * 8 + (lane & 3) * 2;
            const size_t o_lo = ((size_t)(b * Ss + s_lo)) * Dd + h * DKk + dk;
            const size_t o_hi = ((size_t)(b * Ss + s_hi)) * Dd + h * DKk + dk;
            float v0 = o[mt][ni][0] * inv_lo, v1 = o[mt][ni][1] * inv_lo;
            float v2 = o[mt][ni][2] * inv_hi, v3 = o[mt][ni][3] * inv_hi;
            uint32_t hp0 = packbf(v0, v1), hp1 = packbf(v2, v3);
            *(uint32_t*)&Xhi[o_lo] = hp0;
            *(uint32_t*)&Xhi[o_hi] = hp1;
            *(uint32_t*)&Xlo[o_lo] = packbf(v0 - bflo_f(hp0), v1 - bfhi_f(hp0));
            *(uint32_t*)&Xlo[o_hi] = packbf(v2 - bflo_f(hp1), v3 - bfhi_f(hp1));
        }
    }
    #undef ISSUE_KV
}

// ---------------------------------------------------------------------------
extern "C" void kernel_launch(void* const* d_in, const int* in_sizes, int n_in,
                              void* d_out, int out_size)
{
    const float* q   = (const float*)d_in[0];
    const float* k   = (const float*)d_in[1];
    const float* v   = (const float*)d_in[2];
    // d_in[3] = causal mask (int32) — causality computed analytically
    const float* w_q = (const float*)d_in[4];
    const float* b_q = (const float*)d_in[5];
    const float* w_k = (const float*)d_in[6];
    const float* b_k = (const float*)d_in[7];
    const float* w_v = (const float*)d_in[8];
    const float* b_v = (const float*)d_in[9];
    const float* w_o = (const float*)d_in[10];
    const float* b_o = (const float*)d_in[11];
    float* out = (float*)d_out;

    __nv_bfloat16 *pQh, *pQl, *pKh, *pKl, *pVh, *pVl, *pXh, *pXl;
    cudaGetSymbolAddress((void**)&pQh, g_Qhi);
    cudaGetSymbolAddress((void**)&pQl, g_Qlo);
    cudaGetSymbolAddress((void**)&pKh, g_Khi);
    cudaGetSymbolAddress((void**)&pKl, g_Klo);
    cudaGetSymbolAddress((void**)&pVh, g_Vthi);
    cudaGetSymbolAddress((void**)&pVl, g_Vtlo);
    cudaGetSymbolAddress((void**)&pXh, g_Xhi);
    cudaGetSymbolAddress((void**)&pXl, g_Xlo);

    cudaFuncSetAttribute(hgemm_qkv,
                         cudaFuncAttributeMaxDynamicSharedMemorySize, GSMEM);
    cudaFuncSetAttribute(hgemm_out,
                         cudaFuncAttributeMaxDynamicSharedMemorySize, GSMEM);
    cudaFuncSetAttribute(attn_mma_kernel,
                         cudaFuncAttributeMaxDynamicSharedMemorySize, ATTN_SMEM);

    // conversions (weights + activations)
    dim3 wt_grid(32, 32, 4), wt_block(32, 8);
    conv_wt_all<<<wt_grid, wt_block>>>(w_q, w_k, w_v, w_o);
    dim3 ca_grid(4096, 3);
    conv_act_all<<<ca_grid, 256>>>(q, k, v);

    // batched QKV projections (128x128 tiles, 2 CTAs/SM)
    dim3 gemm_grid(Dd / 128, Mm / 128, 3);             // (8, 32, 3)
    hgemm_qkv<<<gemm_grid, 256, GSMEM>>>(b_q, b_k, b_v);

    // attention (128 query rows per CTA)
    dim3 agrid(Ss / QROWS, Bb * Hh);                   // (16, 32)
    attn_mma_kernel<<<agrid, 128, ATTN_SMEM>>>(pQh, pQl, pKh, pKl, pVh, pVl, pXh, pXl);

    // output projection
    dim3 gemm_grid1(Dd / 128, Mm / 128, 1);            // (8, 32)
    hgemm_out<<<gemm_grid1, 256, GSMEM>>>(b_o, out);
}

// round 13
// speedup vs baseline: 1.0273x; 1.0273x over previous
#include <cuda_runtime.h>
#include <cuda_bf16.h>
#include <cstdint>

#define Bb  2
#define Ss  2048
#define Dd  1024
#define Hh  16
#define DKk 64
#define Mm  (Bb*Ss)

// ---------------- scratch (allocation-free: device globals) ----------------
__device__ __nv_bfloat16 g_W0hi[(size_t)Dd*Dd], g_W0lo[(size_t)Dd*Dd];
__device__ __nv_bfloat16 g_W1hi[(size_t)Dd*Dd], g_W1lo[(size_t)Dd*Dd];
__device__ __nv_bfloat16 g_W2hi[(size_t)Dd*Dd], g_W2lo[(size_t)Dd*Dd];
__device__ __nv_bfloat16 g_W3hi[(size_t)Dd*Dd], g_W3lo[(size_t)Dd*Dd];
__device__ __nv_bfloat16 g_Qhi[(size_t)Bb*Hh*Ss*DKk], g_Qlo[(size_t)Bb*Hh*Ss*DKk];
__device__ __nv_bfloat16 g_Khi[(size_t)Bb*Hh*Ss*DKk], g_Klo[(size_t)Bb*Hh*Ss*DKk];
__device__ __nv_bfloat16 g_Vthi[(size_t)Bb*Hh*DKk*Ss], g_Vtlo[(size_t)Bb*Hh*DKk*Ss];
__device__ __nv_bfloat16 g_Xhi[(size_t)Mm*Dd], g_Xlo[(size_t)Mm*Dd];

// ---------------- helpers (arch-portable PTX) --------
__device__ __forceinline__ uint32_t smem_u32(const void* p) {
    uint32_t a;
    asm("{ .reg .u64 t; cvta.to.shared.u64 t, %1; cvt.u32.u64 %0, t; }"
        : "=r"(a) : "l"(p));
    return a;
}
__device__ __forceinline__ void ldsm4(uint32_t a, uint32_t& r0, uint32_t& r1,
                                      uint32_t& r2, uint32_t& r3) {
    asm volatile("ldmatrix.sync.aligned.m8n8.x4.shared.b16 {%0,%1,%2,%3}, [%4];"
                 : "=r"(r0), "=r"(r1), "=r"(r2), "=r"(r3) : "r"(a));
}
__device__ __forceinline__ void mma16816(float* c, uint32_t a0, uint32_t a1,
                                         uint32_t a2, uint32_t a3,
                                         uint32_t b0, uint32_t b1) {
    asm volatile(
        "mma.sync.aligned.m16n8k16.row.col.f32.bf16.bf16.f32 "
        "{%0,%1,%2,%3}, {%4,%5,%6,%7}, {%8,%9}, {%0,%1,%2,%3};"
        : "+f"(c[0]), "+f"(c[1]), "+f"(c[2]), "+f"(c[3])
        : "r"(a0), "r"(a1), "r"(a2), "r"(a3), "r"(b0), "r"(b1));
}
__device__ __forceinline__ uint32_t packbf(float lo, float hi) {
    uint32_t r;
    asm("cvt.rn.bf16x2.f32 %0, %1, %2;" : "=r"(r) : "f"(hi), "f"(lo));
    return r;
}
__device__ __forceinline__ float bflo_f(uint32_t p) { return __uint_as_float(p << 16); }
__device__ __forceinline__ float bfhi_f(uint32_t p) { return __uint_as_float(p & 0xffff0000u); }
__device__ __forceinline__ float ex2f(float x) {
    float r;
    asm("ex2.approx.f32 %0, %1;" : "=f"(r) : "f"(x));
    return r;
}

__device__ __forceinline__ void cpasync16(uint32_t saddr, const void* g) {
    asm volatile("cp.async.ca.shared.global [%0], [%1], 16;"
                 :: "r"(saddr), "l"(g) : "memory");
}
#define CP_COMMIT() asm volatile("cp.async.commit_group;" ::: "memory")
#define CP_WAIT0()  asm volatile("cp.async.wait_group 0;" ::: "memory")

// ---------------------------------------------------------------------------
// merged weight transpose + split: W[K,N] -> WT[N,K] hi/lo, 4 weights
// ---------------------------------------------------------------------------
__global__ __launch_bounds__(256) void conv_wt_all(
    const float* __restrict__ w0, const float* __restrict__ w1,
    const float* __restrict__ w2, const float* __restrict__ w3)
{
    __shared__ float ts[32][33];
    const int z = blockIdx.z;
    const float* W = (z == 0) ? w0 : (z == 1) ? w1 : (z == 2) ? w2 : w3;
    __nv_bfloat16* hiT = (z == 0) ? g_W0hi : (z == 1) ? g_W1hi : (z == 2) ? g_W2hi : g_W3hi;
    __nv_bfloat16* loT = (z == 0) ? g_W0lo : (z == 1) ? g_W1lo : (z == 2) ? g_W2lo : g_W3lo;
    int tx = threadIdx.x, ty = threadIdx.y;          // 32 x 8
    int bn = blockIdx.x * 32, bk = blockIdx.y * 32;
    #pragma unroll
    for (int r = 0; r < 4; r++)
        ts[ty + r * 8][tx] = W[(size_t)(bk + ty + r * 8) * Dd + bn + tx];
    __syncthreads();
    #pragma unroll
    for (int r = 0; r < 4; r++) {
        float x = ts[tx][ty + r * 8];
        __nv_bfloat16 h = __float2bfloat16(x);
        size_t o = (size_t)(bn + ty + r * 8) * Dd + bk + tx;
        hiT[o] = h;
        loT[o] = __float2bfloat16(x - __bfloat162float(h));
    }
}

// ---------------------------------------------------------------------------
// HMMA bf16x3 GEMM body: cp.async double-buffered, 2 CTAs/SM.
// CTA 128x128, K-chunk 32, 8 warps (2m x 4n), warp tile 64x32.
// Fragment reuse across the 3 passes (R10).
// AF=true: A is raw fp32; converted to bf16 hi/lo in-kernel via smem staging.
// mode 0: fp32 row-major; 1: bf16 hi/lo [B,H,S,DK]; 2: bf16 hi/lo [B,H,DK,S].
// ---------------------------------------------------------------------------
#define KCH   32
#define NCHUNK (Dd / KCH)          // 32
#define SROW  40                   // padded halves per row
#define ABYTES (128 * SROW * 2)    // 10240 B per array
#define BUFB  (4 * ABYTES)         // 40960 B per stage
#define STG_OFF (2 * BUFB)         // fp32 staging (AF only)
#define GSMEM    (2 * BUFB)        // 81920 B  (AF=false)
#define GSMEM_F  (2 * BUFB + 16384)// 98304 B  (AF=true)

template<bool AF>
__device__ __forceinline__ void hgemm_body(
    const float* __restrict__ Af,
    const __nv_bfloat16* __restrict__ Ahi, const __nv_bfloat16* __restrict__ Alo,
    const __nv_bfloat16* __restrict__ Whi, const __nv_bfloat16* __restrict__ Wlo,
    const float* __restrict__ bias, float* __restrict__ Cf,
    __nv_bfloat16* __restrict__ Chi, __nv_bfloat16* __restrict__ Clo,
    int mode, __nv_bfloat16* sm)
{
    const int tid  = threadIdx.x;
    const int wid  = tid >> 5, lane = tid & 31;
    const int bm   = blockIdx.y * 128, bn = blockIdx.x * 128;
    const int wm   = wid & 1, wn = wid >> 1;
    char* smc = (char*)sm;

    float c[4][4][4];
    #pragma unroll
    for (int i = 0; i < 4; i++)
        #pragma unroll
        for (int j = 0; j < 4; j++)
            #pragma unroll
            for (int r = 0; r < 4; r++) c[i][j][r] = 0.f;

    const int r0 = tid >> 2,         q0 = (tid & 3) * 8;
    const int r1 = (tid + 256) >> 2, q1 = ((tid + 256) & 3) * 8;
    const uint32_t sb = smem_u32(sm);

    // W loader (arrays 2,3 of a stage)
    #define ISSUE_W(cc, base) do {                                              \
        const int k0_ = (cc) * KCH;                                             \
        cpasync16((base) + (uint32_t)((2 * 128 * SROW + r0 * SROW + q0) * 2),   \
                  &Whi[(size_t)(bn + r0) * Dd + k0_ + q0]);                     \
        cpasync16((base) + (uint32_t)((2 * 128 * SROW + r1 * SROW + q1) * 2),   \
                  &Whi[(size_t)(bn + r1) * Dd + k0_ + q1]);                     \
        cpasync16((base) + (uint32_t)((3 * 128 * SROW + r0 * SROW + q0) * 2),   \
                  &Wlo[(size_t)(bn + r0) * Dd + k0_ + q0]);                     \
        cpasync16((base) + (uint32_t)((3 * 128 * SROW + r1 * SROW + q1) * 2),   \
                  &Wlo[(size_t)(bn + r1) * Dd + k0_ + q1]);                     \
    } while (0)
    // A bf16 loader (arrays 0,1) — used when AF=false
    #define ISSUE_ABF(cc, base) do {                                            \
        const int k0_ = (cc) * KCH;                                             \
        cpasync16((base) + (uint32_t)((0 * 128 * SROW + r0 * SROW + q0) * 2),   \
                  &Ahi[(size_t)(bm + r0) * Dd + k0_ + q0]);                     \
        cpasync16((base) + (uint32_t)((0 * 128 * SROW + r1 * SROW + q1) * 2),   \
                  &Ahi[(size_t)(bm + r1) * Dd + k0_ + q1]);                     \
        cpasync16((base) + (uint32_t)((1 * 128 * SROW + r0 * SROW + q0) * 2),   \
                  &Alo[(size_t)(bm + r0) * Dd + k0_ + q0]);                     \
        cpasync16((base) + (uint32_t)((1 * 128 * SROW + r1 * SROW + q1) * 2),   \
                  &Alo[(size_t)(bm + r1) * Dd + k0_ + q1]);                     \
    } while (0)
    // A fp32 loader into staging — used when AF=true (16KB: 1024 x 16B units)
    #define ISSUE_AF32(cc) do {                                                 \
        const int k0_ = (cc) * KCH;                                             \
        _Pragma("unroll")                                                       \
        for (int t_ = 0; t_ < 4; t_++) {                                        \
            int idx_ = tid + t_ * 256;                                          \
            int row_ = idx_ >> 3, u_ = idx_ & 7;                                \
            cpasync16(sb + (uint32_t)STG_OFF + (uint32_t)(row_ * 128 + u_ * 16),\
                      &Af[(size_t)(bm + row_) * Dd + k0_ + u_ * 4]);            \
        }                                                                       \
    } while (0)

    const uint32_t aoff =
        (uint32_t)(((wm * 64 + (lane & 15)) * SROW + (lane >> 4) * 8) * 2);
    const uint32_t boff4 =
        (uint32_t)(((wn * 32 + (lane >> 4) * 8 + (lane & 7)) * SROW
                    + ((lane >> 3) & 1) * 8) * 2);

    ISSUE_W(0, sb);
    if (AF) ISSUE_AF32(0); else ISSUE_ABF(0, sb);
    CP_COMMIT();

    const int crow = tid >> 1, csub = tid & 1;   // conversion mapping (AF)

    for (int cc = 0; cc < NCHUNK; cc++) {
        CP_WAIT0();
        __syncthreads();

        const uint32_t bufb = sb + (uint32_t)(cc & 1) * BUFB;
        if (AF) {
            // convert fp32 staging -> bf16 hi/lo arrays of stage (cc&1)
            float f[16];
            const char* stg = smc + STG_OFF;
            #pragma unroll
            for (int jj = 0; jj < 4; jj++)
                *(float4*)&f[jj * 4] =
                    *(const float4*)(stg + crow * 128 + csub * 64 + jj * 16);
            uint32_t hi8[8], lo8[8];
            #pragma unroll
            for (int jj = 0; jj < 8; jj++) {
                uint32_t hp = packbf(f[2 * jj], f[2 * jj + 1]);
                hi8[jj] = hp;
                lo8[jj] = packbf(f[2 * jj] - bflo_f(hp), f[2 * jj + 1] - bfhi_f(hp));
            }
            char* ab = smc + (size_t)(cc & 1) * BUFB;
            const uint32_t ro = (uint32_t)((crow * SROW + csub * 16) * 2);
            *(uint4*)(ab + ro)      = *(uint4*)&hi8[0];
            *(uint4*)(ab + ro + 16) = *(uint4*)&hi8[4];
            *(uint4*)(ab + ABYTES + ro)      = *(uint4*)&lo8[0];
            *(uint4*)(ab + ABYTES + ro + 16) = *(uint4*)&lo8[4];
            __syncthreads();   // A bf16 visible; staging free for next chunk
        }

        if (cc + 1 < NCHUNK) {
            const uint32_t nb = sb + (uint32_t)((cc + 1) & 1) * BUFB;
            ISSUE_W(cc + 1, nb);
            if (AF) ISSUE_AF32(cc + 1); else ISSUE_ABF(cc + 1, nb);
            CP_COMMIT();
        }

        #pragma unroll
        for (int ks = 0; ks < 2; ks++) {
            uint32_t ah[4][4], bh[4][2], bl[4][2];
            #pragma unroll
            for (int mi = 0; mi < 4; mi++)
                ldsm4(bufb + aoff + mi * (16 * SROW * 2) + ks * 32,
                      ah[mi][0], ah[mi][1], ah[mi][2], ah[mi][3]);
            #pragma unroll
            for (int nb2 = 0; nb2 < 2; nb2++)
                ldsm4(bufb + 2u * ABYTES + boff4 + nb2 * (16 * SROW * 2) + ks * 32,
                      bh[2 * nb2][0], bh[2 * nb2][1], bh[2 * nb2 + 1][0], bh[2 * nb2 + 1][1]);
            #pragma unroll
            for (int nb2 = 0; nb2 < 2; nb2++)
                ldsm4(bufb + 3u * ABYTES + boff4 + nb2 * (16 * SROW * 2) + ks * 32,
                      bl[2 * nb2][0], bl[2 * nb2][1], bl[2 * nb2 + 1][0], bl[2 * nb2 + 1][1]);
            #pragma unroll
            for (int mi = 0; mi < 4; mi++)
                #pragma unroll
                for (int ni = 0; ni < 4; ni++)
                    mma16816(c[mi][ni], ah[mi][0], ah[mi][1], ah[mi][2], ah[mi][3],
                             bh[ni][0], bh[ni][1]);
            #pragma unroll
            for (int mi = 0; mi < 4; mi++)
                #pragma unroll
                for (int ni = 0; ni < 4; ni++)
                    mma16816(c[mi][ni], ah[mi][0], ah[mi][1], ah[mi][2], ah[mi][3],
                             bl[ni][0], bl[ni][1]);
            #pragma unroll
            for (int mi = 0; mi < 4; mi++)
                ldsm4(bufb + (uint32_t)ABYTES + aoff + mi * (16 * SROW * 2) + ks * 32,
                      ah[mi][0], ah[mi][1], ah[mi][2], ah[mi][3]);
            #pragma unroll
            for (int mi = 0; mi < 4; mi++)
                #pragma unroll
                for (int ni = 0; ni < 4; ni++)
                    mma16816(c[mi][ni], ah[mi][0], ah[mi][1], ah[mi][2], ah[mi][3],
                             bh[ni][0], bh[ni][1]);
        }
    }

    // ---- epilogue ----
    const int mrow0 = bm + wm * 64 + (lane >> 2);
    const int ncol0 = bn + wn * 32 + (lane & 3) * 2;
    #pragma unroll
    for (int mi = 0; mi < 4; mi++) {
        #pragma unroll
        for (int h2 = 0; h2 < 2; h2++) {
            const int m = mrow0 + mi * 16 + h2 * 8;
            const int b = m >> 11, s = m & 2047;
            #pragma unroll
            for (int ni = 0; ni < 4; ni++) {
                const int n = ncol0 + ni * 8;
                float v0 = c[mi][ni][h2 * 2 + 0] + bias[n];
                float v1 = c[mi][ni][h2 * 2 + 1] + bias[n + 1];
                if (mode == 0) {
                    float2 v; v.x = v0; v.y = v1;
                    *(float2*)&Cf[(size_t)m * Dd + n] = v;
                } else {
                    const int h = n >> 6, dk = n & 63;
                    uint32_t hp = packbf(v0, v1);
                    uint32_t lp = packbf(v0 - bflo_f(hp), v1 - bfhi_f(hp));
                    if (mode == 1) {
                        size_t o = (((size_t)(b * Hh + h)) * Ss + s) * DKk + dk;
                        *(uint32_t*)&Chi[o] = hp;
                        *(uint32_t*)&Clo[o] = lp;
                    } else {
                        size_t o = (((size_t)(b * Hh + h)) * DKk + dk) * Ss + s;
                        Chi[o]      = __ushort_as_bfloat16((uint16_t)(hp & 0xffff));
                        Chi[o + Ss] = __ushort_as_bfloat16((uint16_t)(hp >> 16));
                        Clo[o]      = __ushort_as_bfloat16((uint16_t)(lp & 0xffff));
                        Clo[o + Ss] = __ushort_as_bfloat16((uint16_t)(lp >> 16));
                    }
                }
            }
        }
    }
    #undef ISSUE_W
    #undef ISSUE_ABF
    #undef ISSUE_AF32
}

// batched QKV projections with fused fp32->bf16x2 conversion
__global__ __launch_bounds__(256, 2) void hgemm_qkv(
    const float* __restrict__ q, const float* __restrict__ k,
    const float* __restrict__ v,
    const float* __restrict__ b_q, const float* __restrict__ b_k,
    const float* __restrict__ b_v)
{
    extern __shared__ __nv_bfloat16 smg[];
    const int z = blockIdx.z;
    if (z == 0)
        hgemm_body<true>(q, nullptr, nullptr, g_W0hi, g_W0lo, b_q,
                         nullptr, g_Qhi, g_Qlo, 1, smg);
    else if (z == 1)
        hgemm_body<true>(k, nullptr, nullptr, g_W1hi, g_W1lo, b_k,
                         nullptr, g_Khi, g_Klo, 1, smg);
    else
        hgemm_body<true>(v, nullptr, nullptr, g_W2hi, g_W2lo, b_v,
                         nullptr, g_Vthi, g_Vtlo, 2, smg);
}

__global__ __launch_bounds__(256, 2) void hgemm_out(
    const float* __restrict__ b_o, float* __restrict__ out)
{
    extern __shared__ __nv_bfloat16 smg[];
    hgemm_body<false>(nullptr, g_Xhi, g_Xlo, g_W3hi, g_W3lo, b_o,
                      out, nullptr, nullptr, 0, smg);
}

// ---------------------------------------------------------------------------
// HMMA flash attention, bf16x3, causal, cp.async double-buffered KV.
// CTA: 64 query rows of one (b,h); 4 warps x 16 rows. KV tiles of 64 keys.
// (R10 form — best measured variant)
// ---------------------------------------------------------------------------
#define APAD 72
#define A_TILE (64 * APAD)             // 4608 halves = 9216 B
#define STAGE_H (4 * A_TILE)           // KH,KL,VH,VL per stage
#define ATTN_SMEM ((2 * A_TILE + 2 * STAGE_H) * 2)   // 92160 B
#define SCL2 0.18033688f               // 0.125 * log2(e)

__global__ __launch_bounds__(128, 1) void attn_mma_kernel(
    const __nv_bfloat16* __restrict__ Qhi, const __nv_bfloat16* __restrict__ Qlo,
    const __nv_bfloat16* __restrict__ Khi, const __nv_bfloat16* __restrict__ Klo,
    const __nv_bfloat16* __restrict__ Vthi, const __nv_bfloat16* __restrict__ Vtlo,
    __nv_bfloat16* __restrict__ Xhi, __nv_bfloat16* __restrict__ Xlo)
{
    extern __shared__ __nv_bfloat16 smA[];
    const int tid  = threadIdx.x;
    const int w    = tid >> 5, lane = tid & 31;
    const int bh   = blockIdx.y;
    const int iq   = gridDim.x - 1 - blockIdx.x;   // long CTAs first
    const size_t baseQK = (size_t)bh * Ss * DKk;
    const size_t baseV  = (size_t)bh * DKk * Ss;
    const uint32_t sb = smem_u32(smA);

    #define ISSUE_KV(j, stg) do {                                               \
        const __nv_bfloat16* Kh_g = Khi + baseQK + (size_t)(j) * 64 * DKk;      \
        const __nv_bfloat16* Kl_g = Klo + baseQK + (size_t)(j) * 64 * DKk;      \
        const __nv_bfloat16* Vh_g = Vthi + baseV + (size_t)(j) * 64;            \
        const __nv_bfloat16* Vl_g = Vtlo + baseV + (size_t)(j) * 64;            \
        const uint32_t st = sb + (uint32_t)((2 * A_TILE + (stg) * STAGE_H) * 2);\
        _Pragma("unroll")                                                       \
        for (int t = 0; t < 4; t++) {                                           \
            int idx = tid + t * 128;                                            \
            int row = idx >> 3, cu = (idx & 7) * 8;                             \
            cpasync16(st + (uint32_t)((0 * A_TILE + row * APAD + cu) * 2),      \
                      &Kh_g[row * DKk + cu]);                                   \
            cpasync16(st + (uint32_t)((1 * A_TILE + row * APAD + cu) * 2),      \
                      &Kl_g[row * DKk + cu]);                                   \
            cpasync16(st + (uint32_t)((2 * A_TILE + row * APAD + cu) * 2),      \
                      &Vh_g[(size_t)row * Ss + cu]);                            \
            cpasync16(st + (uint32_t)((3 * A_TILE + row * APAD + cu) * 2),      \
                      &Vl_g[(size_t)row * Ss + cu]);                            \
        }                                                                       \
        CP_COMMIT();                                                            \
    } while (0)

    // ---- load Q tile (64x64 hi/lo) + prefetch KV tile 0 ----
    {
        const __nv_bfloat16* Qh_g = Qhi + baseQK + (size_t)iq * 64 * DKk;
        const __nv_bfloat16* Ql_g = Qlo + baseQK + (size_t)iq * 64 * DKk;
        #pragma unroll
        for (int t = 0; t < 4; t++) {
            int idx = tid + t * 128;
            int row = idx >> 3, cu = (idx & 7) * 8;
            *(uint4*)&smA[0 * A_TILE + row * APAD + cu] = *(const uint4*)&Qh_g[row * DKk + cu];
            *(uint4*)&smA[1 * A_TILE + row * APAD + cu] = *(const uint4*)&Ql_g[row * DKk + cu];
        }
    }
    ISSUE_KV(0, 0);
    __syncthreads();

    const uint32_t a_off = (uint32_t)(((w * 16 + (lane & 15)) * APAD + (lane >> 4) * 8) * 2);
    const uint32_t b_off = (uint32_t)((((lane & 15)) * APAD + (lane >> 4) * 8) * 2);

    uint32_t qh[4][4], ql[4][4];
    #pragma unroll
    for (int kk = 0; kk < 4; kk++) {
        ldsm4(sb + 0 * A_TILE * 2 + a_off + kk * 32, qh[kk][0], qh[kk][1], qh[kk][2], qh[kk][3]);
        ldsm4(sb + 1 * A_TILE * 2 + a_off + kk * 32, ql[kk][0], ql[kk][1], ql[kk][2], ql[kk][3]);
    }

    float o[8][4];
    #pragma unroll
    for (int i = 0; i < 8; i++)
        #pragma unroll
        for (int r = 0; r < 4; r++) o[i][r] = 0.f;
    float m_lo = -1e30f, m_hi = -1e30f, l_lo = 0.f, l_hi = 0.f;

    for (int j = 0; j <= iq; j++) {
        CP_WAIT0();
        __syncthreads();
        if (j < iq) ISSUE_KV(j + 1, (j + 1) & 1);

        const uint32_t stb = sb + (uint32_t)((2 * A_TILE + (j & 1) * STAGE_H) * 2);

        // ---- scores S = Q K^T (3-term) ----
        float s[8][4];
        #pragma unroll
        for (int i = 0; i < 8; i++)
            #pragma unroll
            for (int r = 0; r < 4; r++) s[i][r] = 0.f;

        #pragma unroll
        for (int kk = 0; kk < 4; kk++) {
            uint32_t kh[8][2], kl[8][2];
            #pragma unroll
            for (int np = 0; np < 4; np++) {
                uint32_t t0, t1, t2, t3;
                ldsm4(stb + 0 * A_TILE * 2 + b_off + np * (16 * APAD * 2) + kk * 32, t0, t1, t2, t3);
                kh[2 * np][0] = t0; kh[2 * np][1] = t2;
                kh[2 * np + 1][0] = t1; kh[2 * np + 1][1] = t3;
                ldsm4(stb + 1 * A_TILE * 2 + b_off + np * (16 * APAD * 2) + kk * 32, t0, t1, t2, t3);
                kl[2 * np][0] = t0; kl[2 * np][1] = t2;
                kl[2 * np + 1][0] = t1; kl[2 * np + 1][1] = t3;
            }
            #pragma unroll
            for (int ni = 0; ni < 8; ni++)
                mma16816(s[ni], qh[kk][0], qh[kk][1], qh[kk][2], qh[kk][3],
                         kh[ni][0], kh[ni][1]);
            #pragma unroll
            for (int ni = 0; ni < 8; ni++)
                mma16816(s[ni], qh[kk][0], qh[kk][1], qh[kk][2], qh[kk][3],
                         kl[ni][0], kl[ni][1]);
            #pragma unroll
            for (int ni = 0; ni < 8; ni++)
                mma16816(s[ni], ql[kk][0], ql[kk][1], ql[kk][2], ql[kk][3],
                         kh[ni][0], kh[ni][1]);
        }

        // ---- scale into exp2 domain + causal mask (diagonal tile only) ----
        #pragma unroll
        for (int ni = 0; ni < 8; ni++)
            #pragma unroll
            for (int r = 0; r < 4; r++) s[ni][r] *= SCL2;
        if (j == iq) {
            const int rlo = w * 16 + (lane >> 2), rhi = rlo + 8;
            #pragma unroll
            for (int ni = 0; ni < 8; ni++) {
                const int c0 = ni * 8 + (lane & 3) * 2;
                if (c0 > rlo)     s[ni][0] = -1e30f;
                if (c0 + 1 > rlo) s[ni][1] = -1e30f;
                if (c0 > rhi)     s[ni][2] = -1e30f;
                if (c0 + 1 > rhi) s[ni][3] = -1e30f;
            }
        }

        // ---- online softmax (fp32, base-2) ----
        float mx_lo = s[0][0], mx_hi = s[0][2];
        #pragma unroll
        for (int ni = 0; ni < 8; ni++) {
            mx_lo = fmaxf(mx_lo, fmaxf(s[ni][0], s[ni][1]));
            mx_hi = fmaxf(mx_hi, fmaxf(s[ni][2], s[ni][3]));
        }
        mx_lo = fmaxf(mx_lo, __shfl_xor_sync(0xffffffffu, mx_lo, 1));
        mx_lo = fmaxf(mx_lo, __shfl_xor_sync(0xffffffffu, mx_lo, 2));
        mx_hi = fmaxf(mx_hi, __shfl_xor_sync(0xffffffffu, mx_hi, 1));
        mx_hi = fmaxf(mx_hi, __shfl_xor_sync(0xffffffffu, mx_hi, 2));
        const float mn_lo = fmaxf(m_lo, mx_lo), mn_hi = fmaxf(m_hi, mx_hi);
        const float al_lo = ex2f(m_lo - mn_lo), al_hi = ex2f(m_hi - mn_hi);

        uint32_t ph[8][2], pl[8][2];
        float sum_lo = 0.f, sum_hi = 0.f;
        #pragma unroll
        for (int ni = 0; ni < 8; ni++) {
            float p0 = ex2f(s[ni][0] - mn_lo);
            float p1 = ex2f(s[ni][1] - mn_lo);
            float p2 = ex2f(s[ni][2] - mn_hi);
            float p3 = ex2f(s[ni][3] - mn_hi);
            sum_lo += p0 + p1; sum_hi += p2 + p3;
            uint32_t h01 = packbf(p0, p1), h23 = packbf(p2, p3);
            ph[ni][0] = h01; ph[ni][1] = h23;
            pl[ni][0] = packbf(p0 - bflo_f(h01), p1 - bfhi_f(h01));
            pl[ni][1] = packbf(p2 - bflo_f(h23), p3 - bfhi_f(h23));
        }
        sum_lo += __shfl_xor_sync(0xffffffffu, sum_lo, 1);
        sum_lo += __shfl_xor_sync(0xffffffffu, sum_lo, 2);
        sum_hi += __shfl_xor_sync(0xffffffffu, sum_hi, 1);
        sum_hi += __shfl_xor_sync(0xffffffffu, sum_hi, 2);
        l_lo = l_lo * al_lo + sum_lo;  m_lo = mn_lo;
        l_hi = l_hi * al_hi + sum_hi;  m_hi = mn_hi;
        #pragma unroll
        for (int ni = 0; ni < 8; ni++) {
            o[ni][0] *= al_lo; o[ni][1] *= al_lo;
            o[ni][2] *= al_hi; o[ni][3] *= al_hi;
        }

        // ---- O += P V (3-term) ----
        #pragma unroll
        for (int kk = 0; kk < 4; kk++) {
            uint32_t vh[8][2], vl[8][2];
            #pragma unroll
            for (int np = 0; np < 4; np++) {
                uint32_t t0, t1, t2, t3;
                ldsm4(stb + 2 * A_TILE * 2 + b_off + np * (16 * APAD * 2) + kk * 32, t0, t1, t2, t3);
                vh[2 * np][0] = t0; vh[2 * np][1] = t2;
                vh[2 * np + 1][0] = t1; vh[2 * np + 1][1] = t3;
                ldsm4(stb + 3 * A_TILE * 2 + b_off + np * (16 * APAD * 2) + kk * 32, t0, t1, t2, t3);
                vl[2 * np][0] = t0; vl[2 * np][1] = t2;
                vl[2 * np + 1][0] = t1; vl[2 * np + 1][1] = t3;
            }
            const uint32_t pa0 = ph[2 * kk][0], pa1 = ph[2 * kk][1];
            const uint32_t pa2 = ph[2 * kk + 1][0], pa3 = ph[2 * kk + 1][1];
            const uint32_t qa0 = pl[2 * kk][0], qa1 = pl[2 * kk][1];
            const uint32_t qa2 = pl[2 * kk + 1][0], qa3 = pl[2 * kk + 1][1];
            #pragma unroll
            for (int ni = 0; ni < 8; ni++)
                mma16816(o[ni], pa0, pa1, pa2, pa3, vh[ni][0], vh[ni][1]);
            #pragma unroll
            for (int ni = 0; ni < 8; ni++)
                mma16816(o[ni], pa0, pa1, pa2, pa3, vl[ni][0], vl[ni][1]);
            #pragma unroll
            for (int ni = 0; ni < 8; ni++)
                mma16816(o[ni], qa0, qa1, qa2, qa3, vh[ni][0], vh[ni][1]);
        }
    }

    // ---- epilogue: X[b, s, h*64+dk] as bf16 hi/lo ----
    const float inv_lo = 1.f / l_lo, inv_hi = 1.f / l_hi;
    const int b = bh >> 4, h = bh & 15;
    const int s_lo = iq * 64 + w * 16 + (lane >> 2);
    const int s_hi = s_lo + 8;
    #pragma unroll
    for (int ni = 0; ni < 8; ni++) {
        const int dk = ni * 8 + (lane & 3) * 2;
        const size_t o_lo = ((size_t)(b * Ss + s_lo)) * Dd + h * DKk + dk;
        const size_t o_hi = ((size_t)(b * Ss + s_hi)) * Dd + h * DKk + dk;
        float v0 = o[ni][0] * inv_lo, v1 = o[ni][1] * inv_lo;
        float v2 = o[ni][2] * inv_hi, v3 = o[ni][3] * inv_hi;
        uint32_t hp0 = packbf(v0, v1), hp1 = packbf(v2, v3);
        *(uint32_t*)&Xhi[o_lo] = hp0;
        *(uint32_t*)&Xhi[o_hi] = hp1;
        *(uint32_t*)&Xlo[o_lo] = packbf(v0 - bflo_f(hp0), v1 - bfhi_f(hp0));
        *(uint32_t*)&Xlo[o_hi] = packbf(v2 - bflo_f(hp1), v3 - bfhi_f(hp1));
    }
    #undef ISSUE_KV
}

// ---------------------------------------------------------------------------
extern "C" void kernel_launch(void* const* d_in, const int* in_sizes, int n_in,
                              void* d_out, int out_size)
{
    const float* q   = (const float*)d_in[0];
    const float* k   = (const float*)d_in[1];
    const float* v   = (const float*)d_in[2];
    // d_in[3] = causal mask (int32) — causality computed analytically
    const float* w_q = (const float*)d_in[4];
    const float* b_q = (const float*)d_in[5];
    const float* w_k = (const float*)d_in[6];
    const float* b_k = (const float*)d_in[7];
    const float* w_v = (const float*)d_in[8];
    const float* b_v = (const float*)d_in[9];
    const float* w_o = (const float*)d_in[10];
    const float* b_o = (const float*)d_in[11];
    float* out = (float*)d_out;

    __nv_bfloat16 *pQh, *pQl, *pKh, *pKl, *pVh, *pVl, *pXh, *pXl;
    cudaGetSymbolAddress((void**)&pQh, g_Qhi);
    cudaGetSymbolAddress((void**)&pQl, g_Qlo);
    cudaGetSymbolAddress((void**)&pKh, g_Khi);
    cudaGetSymbolAddress((void**)&pKl, g_Klo);
    cudaGetSymbolAddress((void**)&pVh, g_Vthi);
    cudaGetSymbolAddress((void**)&pVl, g_Vtlo);
    cudaGetSymbolAddress((void**)&pXh, g_Xhi);
    cudaGetSymbolAddress((void**)&pXl, g_Xlo);

    cudaFuncSetAttribute(hgemm_qkv,
                         cudaFuncAttributeMaxDynamicSharedMemorySize, GSMEM_F);
    cudaFuncSetAttribute(hgemm_out,
                         cudaFuncAttributeMaxDynamicSharedMemorySize, GSMEM);
    cudaFuncSetAttribute(attn_mma_kernel,
                         cudaFuncAttributeMaxDynamicSharedMemorySize, ATTN_SMEM);

    // weight conversions
    dim3 wt_grid(32, 32, 4), wt_block(32, 8);
    conv_wt_all<<<wt_grid, wt_block>>>(w_q, w_k, w_v, w_o);

    // batched QKV projections (fused fp32 activation conversion)
    dim3 gemm_grid(Dd / 128, Mm / 128, 3);             // (8, 32, 3)
    hgemm_qkv<<<gemm_grid, 256, GSMEM_F>>>(q, k, v, b_q, b_k, b_v);

    // attention
    dim3 agrid(Ss / 64, Bb * Hh);                      // (32, 32)
    attn_mma_kernel<<<agrid, 128, ATTN_SMEM>>>(pQh, pQl, pKh, pKl, pVh, pVl, pXh, pXl);

    // output projection
    dim3 gemm_grid1(Dd / 128, Mm / 128, 1);            // (8, 32)
    hgemm_out<<<gemm_grid1, 256, GSMEM>>>(b_o, out);
}

// round 14
// speedup vs baseline: 1.0525x; 1.0246x over previous
#include <cuda_runtime.h>
#include <cuda_bf16.h>
#include <cstdint>

#define Bb  2
#define Ss  2048
#define Dd  1024
#define Hh  16
#define DKk 64
#define Mm  (Bb*Ss)

#define MOFF  ((size_t)Mm * Dd)        // 4194304 elems: lo-offset for activations
#define WOFF2 ((size_t)Dd * Dd)        // 1048576 elems: lo-offset for weights

// ---------------- scratch (allocation-free: device globals) ----------------
// each array: [hi | lo] halves at +0 / +offset
__device__ __nv_bfloat16 g_A0[2 * MOFF];
__device__ __nv_bfloat16 g_A1[2 * MOFF];
__device__ __nv_bfloat16 g_A2[2 * MOFF];
__device__ __nv_bfloat16 g_W0[2 * WOFF2];
__device__ __nv_bfloat16 g_W1[2 * WOFF2];
__device__ __nv_bfloat16 g_W2[2 * WOFF2];
__device__ __nv_bfloat16 g_W3[2 * WOFF2];
__device__ __nv_bfloat16 g_Q[2 * MOFF];    // [B,H,S,DK]
__device__ __nv_bfloat16 g_K[2 * MOFF];    // [B,H,S,DK]
__device__ __nv_bfloat16 g_Vt[2 * MOFF];   // [B,H,DK,S]
__device__ __nv_bfloat16 g_X[2 * MOFF];    // [B,S,D]

// ---------------- helpers (arch-portable PTX) --------
__device__ __forceinline__ uint32_t smem_u32(const void* p) {
    uint32_t a;
    asm("{ .reg .u64 t; cvta.to.shared.u64 t, %1; cvt.u32.u64 %0, t; }"
        : "=r"(a) : "l"(p));
    return a;
}
__device__ __forceinline__ void ldsm4(uint32_t a, uint32_t& r0, uint32_t& r1,
                                      uint32_t& r2, uint32_t& r3) {
    asm volatile("ldmatrix.sync.aligned.m8n8.x4.shared.b16 {%0,%1,%2,%3}, [%4];"
                 : "=r"(r0), "=r"(r1), "=r"(r2), "=r"(r3) : "r"(a));
}
__device__ __forceinline__ void mma16816(float* c, uint32_t a0, uint32_t a1,
                                         uint32_t a2, uint32_t a3,
                                         uint32_t b0, uint32_t b1) {
    asm volatile(
        "mma.sync.aligned.m16n8k16.row.col.f32.bf16.bf16.f32 "
        "{%0,%1,%2,%3}, {%4,%5,%6,%7}, {%8,%9}, {%0,%1,%2,%3};"
        : "+f"(c[0]), "+f"(c[1]), "+f"(c[2]), "+f"(c[3])
        : "r"(a0), "r"(a1), "r"(a2), "r"(a3), "r"(b0), "r"(b1));
}
__device__ __forceinline__ uint32_t packbf(float lo, float hi) {
    uint32_t r;
    asm("cvt.rn.bf16x2.f32 %0, %1, %2;" : "=r"(r) : "f"(hi), "f"(lo));
    return r;
}
__device__ __forceinline__ float bflo_f(uint32_t p) { return __uint_as_float(p << 16); }
__device__ __forceinline__ float bfhi_f(uint32_t p) { return __uint_as_float(p & 0xffff0000u); }
__device__ __forceinline__ float ex2f(float x) {
    float r;
    asm("ex2.approx.f32 %0, %1;" : "=f"(r) : "f"(x));
    return r;
}

__device__ __forceinline__ void cpasync16(uint32_t saddr, const void* g) {
    asm volatile("cp.async.cg.shared.global [%0], [%1], 16;"
                 :: "r"(saddr), "l"(g) : "memory");
}
#define CP_COMMIT() asm volatile("cp.async.commit_group;" ::: "memory")
#define CP_WAIT0()  asm volatile("cp.async.wait_group 0;" ::: "memory")

// ---------------------------------------------------------------------------
// merged fp32 -> bf16 hi/lo splits for q,k,v activations
// ---------------------------------------------------------------------------
__global__ __launch_bounds__(256) void conv_act_all(
    const float* __restrict__ q, const float* __restrict__ k,
    const float* __restrict__ v)
{
    const float* src = (blockIdx.y == 0) ? q : (blockIdx.y == 1) ? k : v;
    __nv_bfloat16* dst = (blockIdx.y == 0) ? g_A0 : (blockIdx.y == 1) ? g_A1 : g_A2;
    int i = blockIdx.x * blockDim.x + threadIdx.x;
    float4 vv = ((const float4*)src)[i];
    uint32_t h0 = packbf(vv.x, vv.y), h1 = packbf(vv.z, vv.w);
    ((uint32_t*)dst)[i * 2 + 0] = h0;
    ((uint32_t*)dst)[i * 2 + 1] = h1;
    ((uint32_t*)(dst + MOFF))[i * 2 + 0] = packbf(vv.x - bflo_f(h0), vv.y - bfhi_f(h0));
    ((uint32_t*)(dst + MOFF))[i * 2 + 1] = packbf(vv.z - bflo_f(h1), vv.w - bfhi_f(h1));
}

// ---------------------------------------------------------------------------
// merged weight transpose + split: W[K,N] -> WT[N,K] hi/lo, 4 weights
// ---------------------------------------------------------------------------
__global__ __launch_bounds__(256) void conv_wt_all(
    const float* __restrict__ w0, const float* __restrict__ w1,
    const float* __restrict__ w2, const float* __restrict__ w3)
{
    __shared__ float ts[32][33];
    const int z = blockIdx.z;
    const float* W = (z == 0) ? w0 : (z == 1) ? w1 : (z == 2) ? w2 : w3;
    __nv_bfloat16* dst = (z == 0) ? g_W0 : (z == 1) ? g_W1 : (z == 2) ? g_W2 : g_W3;
    int tx = threadIdx.x, ty = threadIdx.y;          // 32 x 8
    int bn = blockIdx.x * 32, bk = blockIdx.y * 32;
    #pragma unroll
    for (int r = 0; r < 4; r++)
        ts[ty + r * 8][tx] = W[(size_t)(bk + ty + r * 8) * Dd + bn + tx];
    __syncthreads();
    #pragma unroll
    for (int r = 0; r < 4; r++) {
        float x = ts[tx][ty + r * 8];
        __nv_bfloat16 h = __float2bfloat16(x);
        size_t o = (size_t)(bn + ty + r * 8) * Dd + bk + tx;
        dst[o] = h;
        dst[WOFF2 + o] = __float2bfloat16(x - __bfloat162float(h));
    }
}

// ---------------------------------------------------------------------------
// HMMA bf16x3 GEMM body: cp.async double-buffered, 2 CTAs/SM. (R10 config)
// CTA 128x128, K-chunk 32, 8 warps (2m x 4n), warp tile 64x32.
// Fragment reuse across the 3 passes: 12 ldsm4/ks.
// A = [hi|lo@+MOFF]; W = [hi|lo@+WOFF2]; C (mode 1/2) = [hi|lo@+MOFF].
// mode 0: fp32 row-major; 1: bf16 [B,H,S,DK]; 2: bf16 [B,H,DK,S].
// ---------------------------------------------------------------------------
#define KCH   32
#define NCHUNK (Dd / KCH)          // 32
#define SROW  40                   // padded halves per row
#define ABYTES (128 * SROW * 2)    // 10240 B per array
#define BUFB  (4 * ABYTES)         // 40960 B per stage
#define GSMEM (2 * BUFB)           // 81920 B

__device__ __forceinline__ void hgemm_body(
    const __nv_bfloat16* __restrict__ A, const __nv_bfloat16* __restrict__ W,
    const float* __restrict__ bias, float* __restrict__ Cf,
    __nv_bfloat16* __restrict__ Cb, int mode, __nv_bfloat16* sm)
{
    const int tid  = threadIdx.x;
    const int wid  = tid >> 5, lane = tid & 31;
    const int bm   = blockIdx.y * 128, bn = blockIdx.x * 128;
    const int wm   = wid & 1, wn = wid >> 1;

    float c[4][4][4];
    #pragma unroll
    for (int i = 0; i < 4; i++)
        #pragma unroll
        for (int j = 0; j < 4; j++)
            #pragma unroll
            for (int r = 0; r < 4; r++) c[i][j][r] = 0.f;

    const int r0 = tid >> 2,         q0 = (tid & 3) * 8;
    const int r1 = (tid + 256) >> 2, q1 = ((tid + 256) & 3) * 8;
    const uint32_t sb = smem_u32(sm);

    #define ISSUE_CHUNK(cc, base) do {                                          \
        const int k0_ = (cc) * KCH;                                             \
        const __nv_bfloat16* a0_ = &A[(size_t)(bm + r0) * Dd + k0_ + q0];       \
        const __nv_bfloat16* a1_ = &A[(size_t)(bm + r1) * Dd + k0_ + q1];       \
        const __nv_bfloat16* w0_ = &W[(size_t)(bn + r0) * Dd + k0_ + q0];       \
        const __nv_bfloat16* w1_ = &W[(size_t)(bn + r1) * Dd + k0_ + q1];       \
        cpasync16((base) + (uint32_t)((0 * 128 * SROW + r0 * SROW + q0) * 2), a0_);         \
        cpasync16((base) + (uint32_t)((0 * 128 * SROW + r1 * SROW + q1) * 2), a1_);         \
        cpasync16((base) + (uint32_t)((1 * 128 * SROW + r0 * SROW + q0) * 2), a0_ + MOFF);  \
        cpasync16((base) + (uint32_t)((1 * 128 * SROW + r1 * SROW + q1) * 2), a1_ + MOFF);  \
        cpasync16((base) + (uint32_t)((2 * 128 * SROW + r0 * SROW + q0) * 2), w0_);         \
        cpasync16((base) + (uint32_t)((2 * 128 * SROW + r1 * SROW + q1) * 2), w1_);         \
        cpasync16((base) + (uint32_t)((3 * 128 * SROW + r0 * SROW + q0) * 2), w0_ + WOFF2); \
        cpasync16((base) + (uint32_t)((3 * 128 * SROW + r1 * SROW + q1) * 2), w1_ + WOFF2); \
        CP_COMMIT();                                                            \
    } while (0)

    const uint32_t aoff =
        (uint32_t)(((wm * 64 + (lane & 15)) * SROW + (lane >> 4) * 8) * 2);
    // B ldsm4: lanes 0-7 -> (n0,k0), 8-15 -> (n0,k8), 16-23 -> (n1,k0), 24-31 -> (n1,k8)
    const uint32_t boff4 =
        (uint32_t)(((wn * 32 + (lane >> 4) * 8 + (lane & 7)) * SROW
                    + ((lane >> 3) & 1) * 8) * 2);

    ISSUE_CHUNK(0, sb);

    for (int cc = 0; cc < NCHUNK; cc++) {
        CP_WAIT0();
        __syncthreads();
        if (cc + 1 < NCHUNK)
            ISSUE_CHUNK(cc + 1, sb + (uint32_t)((cc + 1) & 1) * BUFB);

        const uint32_t bufb = sb + (uint32_t)(cc & 1) * BUFB;
        #pragma unroll
        for (int ks = 0; ks < 2; ks++) {
            uint32_t ah[4][4], bh[4][2], bl[4][2];
            #pragma unroll
            for (int mi = 0; mi < 4; mi++)
                ldsm4(bufb + aoff + mi * (16 * SROW * 2) + ks * 32,
                      ah[mi][0], ah[mi][1], ah[mi][2], ah[mi][3]);
            #pragma unroll
            for (int nb = 0; nb < 2; nb++)
                ldsm4(bufb + 2u * ABYTES + boff4 + nb * (16 * SROW * 2) + ks * 32,
                      bh[2 * nb][0], bh[2 * nb][1], bh[2 * nb + 1][0], bh[2 * nb + 1][1]);
            #pragma unroll
            for (int nb = 0; nb < 2; nb++)
                ldsm4(bufb + 3u * ABYTES + boff4 + nb * (16 * SROW * 2) + ks * 32,
                      bl[2 * nb][0], bl[2 * nb][1], bl[2 * nb + 1][0], bl[2 * nb + 1][1]);
            // pass 0: Ah * Bh
            #pragma unroll
            for (int mi = 0; mi < 4; mi++)
                #pragma unroll
                for (int ni = 0; ni < 4; ni++)
                    mma16816(c[mi][ni], ah[mi][0], ah[mi][1], ah[mi][2], ah[mi][3],
                             bh[ni][0], bh[ni][1]);
            // pass 1: Ah * Bl
            #pragma unroll
            for (int mi = 0; mi < 4; mi++)
                #pragma unroll
                for (int ni = 0; ni < 4; ni++)
                    mma16816(c[mi][ni], ah[mi][0], ah[mi][1], ah[mi][2], ah[mi][3],
                             bl[ni][0], bl[ni][1]);
            // A-lo fragments (overwrite ah)
            #pragma unroll
            for (int mi = 0; mi < 4; mi++)
                ldsm4(bufb + (uint32_t)ABYTES + aoff + mi * (16 * SROW * 2) + ks * 32,
                      ah[mi][0], ah[mi][1], ah[mi][2], ah[mi][3]);
            // pass 2: Al * Bh
            #pragma unroll
            for (int mi = 0; mi < 4; mi++)
                #pragma unroll
                for (int ni = 0; ni < 4; ni++)
                    mma16816(c[mi][ni], ah[mi][0], ah[mi][1], ah[mi][2], ah[mi][3],
                             bh[ni][0], bh[ni][1]);
        }
    }

    // ---- epilogue ----
    const int mrow0 = bm + wm * 64 + (lane >> 2);
    const int ncol0 = bn + wn * 32 + (lane & 3) * 2;
    #pragma unroll
    for (int mi = 0; mi < 4; mi++) {
        #pragma unroll
        for (int h2 = 0; h2 < 2; h2++) {
            const int m = mrow0 + mi * 16 + h2 * 8;
            const int b = m >> 11, s = m & 2047;
            #pragma unroll
            for (int ni = 0; ni < 4; ni++) {
                const int n = ncol0 + ni * 8;
                float v0 = c[mi][ni][h2 * 2 + 0] + bias[n];
                float v1 = c[mi][ni][h2 * 2 + 1] + bias[n + 1];
                if (mode == 0) {
                    float2 v; v.x = v0; v.y = v1;
                    *(float2*)&Cf[(size_t)m * Dd + n] = v;
                } else {
                    const int h = n >> 6, dk = n & 63;
                    uint32_t hp = packbf(v0, v1);
                    uint32_t lp = packbf(v0 - bflo_f(hp), v1 - bfhi_f(hp));
                    if (mode == 1) {
                        size_t o = (((size_t)(b * Hh + h)) * Ss + s) * DKk + dk;
                        *(uint32_t*)&Cb[o] = hp;
                        *(uint32_t*)&Cb[MOFF + o] = lp;
                    } else {
                        size_t o = (((size_t)(b * Hh + h)) * DKk + dk) * Ss + s;
                        Cb[o]      = __ushort_as_bfloat16((uint16_t)(hp & 0xffff));
                        Cb[o + Ss] = __ushort_as_bfloat16((uint16_t)(hp >> 16));
                        Cb[MOFF + o]      = __ushort_as_bfloat16((uint16_t)(lp & 0xffff));
                        Cb[MOFF + o + Ss] = __ushort_as_bfloat16((uint16_t)(lp >> 16));
                    }
                }
            }
        }
    }
    #undef ISSUE_CHUNK
}

// batched QKV projections: blockIdx.z selects {Q, K, V}
__global__ __launch_bounds__(256, 2) void hgemm_qkv(
    const float* __restrict__ b_q, const float* __restrict__ b_k,
    const float* __restrict__ b_v)
{
    extern __shared__ __nv_bfloat16 smg[];
    const int z = blockIdx.z;
    if (z == 0)
        hgemm_body(g_A0, g_W0, b_q, nullptr, g_Q, 1, smg);
    else if (z == 1)
        hgemm_body(g_A1, g_W1, b_k, nullptr, g_K, 1, smg);
    else
        hgemm_body(g_A2, g_W2, b_v, nullptr, g_Vt, 2, smg);
}

__global__ __launch_bounds__(256, 2) void hgemm_out(
    const float* __restrict__ b_o, float* __restrict__ out)
{
    extern __shared__ __nv_bfloat16 smg[];
    hgemm_body(g_X, g_W3, b_o, out, nullptr, 0, smg);
}

// ---------------------------------------------------------------------------
// HMMA flash attention, bf16x3, causal, cp.async double-buffered KV.
// CTA: 64 query rows of one (b,h); 4 warps x 16 rows. KV tiles of 64 keys.
// (R10 form — best measured variant; merged hi/lo pointers)
// ---------------------------------------------------------------------------
#define APAD 72
#define A_TILE (64 * APAD)             // 4608 halves = 9216 B
#define STAGE_H (4 * A_TILE)           // KH,KL,VH,VL per stage
#define ATTN_SMEM ((2 * A_TILE + 2 * STAGE_H) * 2)   // 92160 B
#define SCL2 0.18033688f               // 0.125 * log2(e)

__global__ __launch_bounds__(128, 1) void attn_mma_kernel(
    const __nv_bfloat16* __restrict__ Q, const __nv_bfloat16* __restrict__ K,
    const __nv_bfloat16* __restrict__ Vt, __nv_bfloat16* __restrict__ X)
{
    extern __shared__ __nv_bfloat16 smA[];
    const int tid  = threadIdx.x;
    const int w    = tid >> 5, lane = tid & 31;
    const int bh   = blockIdx.y;
    const int iq   = gridDim.x - 1 - blockIdx.x;   // long CTAs first
    const size_t baseQK = (size_t)bh * Ss * DKk;
    const size_t baseV  = (size_t)bh * DKk * Ss;
    const uint32_t sb = smem_u32(smA);

    #define ISSUE_KV(j, stg) do {                                               \
        const __nv_bfloat16* Kg_ = K + baseQK + (size_t)(j) * 64 * DKk;         \
        const __nv_bfloat16* Vg_ = Vt + baseV + (size_t)(j) * 64;               \
        const uint32_t st = sb + (uint32_t)((2 * A_TILE + (stg) * STAGE_H) * 2);\
        _Pragma("unroll")                                                       \
        for (int t = 0; t < 4; t++) {                                           \
            int idx = tid + t * 128;                                            \
            int row = idx >> 3, cu = (idx & 7) * 8;                             \
            cpasync16(st + (uint32_t)((0 * A_TILE + row * APAD + cu) * 2),      \
                      Kg_ + row * DKk + cu);                                    \
            cpasync16(st + (uint32_t)((1 * A_TILE + row * APAD + cu) * 2),      \
                      Kg_ + MOFF + row * DKk + cu);                             \
            cpasync16(st + (uint32_t)((2 * A_TILE + row * APAD + cu) * 2),      \
                      Vg_ + (size_t)row * Ss + cu);                             \
            cpasync16(st + (uint32_t)((3 * A_TILE + row * APAD + cu) * 2),      \
                      Vg_ + MOFF + (size_t)row * Ss + cu);                      \
        }                                                                       \
        CP_COMMIT();                                                            \
    } while (0)

    // ---- load Q tile (64x64 hi/lo) + prefetch KV tile 0 ----
    {
        const __nv_bfloat16* Qg_ = Q + baseQK + (size_t)iq * 64 * DKk;
        #pragma unroll
        for (int t = 0; t < 4; t++) {
            int idx = tid + t * 128;
            int row = idx >> 3, cu = (idx & 7) * 8;
            *(uint4*)&smA[0 * A_TILE + row * APAD + cu] =
                *(const uint4*)(Qg_ + row * DKk + cu);
            *(uint4*)&smA[1 * A_TILE + row * APAD + cu] =
                *(const uint4*)(Qg_ + MOFF + row * DKk + cu);
        }
    }
    ISSUE_KV(0, 0);
    __syncthreads();

    const uint32_t a_off = (uint32_t)(((w * 16 + (lane & 15)) * APAD + (lane >> 4) * 8) * 2);
    const uint32_t b_off = (uint32_t)((((lane & 15)) * APAD + (lane >> 4) * 8) * 2);

    uint32_t qh[4][4], ql[4][4];
    #pragma unroll
    for (int kk = 0; kk < 4; kk++) {
        ldsm4(sb + 0 * A_TILE * 2 + a_off + kk * 32, qh[kk][0], qh[kk][1], qh[kk][2], qh[kk][3]);
        ldsm4(sb + 1 * A_TILE * 2 + a_off + kk * 32, ql[kk][0], ql[kk][1], ql[kk][2], ql[kk][3]);
    }

    float o[8][4];
    #pragma unroll
    for (int i = 0; i < 8; i++)
        #pragma unroll
        for (int r = 0; r < 4; r++) o[i][r] = 0.f;
    float m_lo = -1e30f, m_hi = -1e30f, l_lo = 0.f, l_hi = 0.f;

    for (int j = 0; j <= iq; j++) {
        CP_WAIT0();
        __syncthreads();
        if (j < iq) ISSUE_KV(j + 1, (j + 1) & 1);

        const uint32_t stb = sb + (uint32_t)((2 * A_TILE + (j & 1) * STAGE_H) * 2);

        // ---- scores S = Q K^T (3-term) ----
        float s[8][4];
        #pragma unroll
        for (int i = 0; i < 8; i++)
            #pragma unroll
            for (int r = 0; r < 4; r++) s[i][r] = 0.f;

        #pragma unroll
        for (int kk = 0; kk < 4; kk++) {
            uint32_t kh[8][2], kl[8][2];
            #pragma unroll
            for (int np = 0; np < 4; np++) {
                uint32_t t0, t1, t2, t3;
                ldsm4(stb + 0 * A_TILE * 2 + b_off + np * (16 * APAD * 2) + kk * 32, t0, t1, t2, t3);
                kh[2 * np][0] = t0; kh[2 * np][1] = t2;
                kh[2 * np + 1][0] = t1; kh[2 * np + 1][1] = t3;
                ldsm4(stb + 1 * A_TILE * 2 + b_off + np * (16 * APAD * 2) + kk * 32, t0, t1, t2, t3);
                kl[2 * np][0] = t0; kl[2 * np][1] = t2;
                kl[2 * np + 1][0] = t1; kl[2 * np + 1][1] = t3;
            }
            #pragma unroll
            for (int ni = 0; ni < 8; ni++)
                mma16816(s[ni], qh[kk][0], qh[kk][1], qh[kk][2], qh[kk][3],
                         kh[ni][0], kh[ni][1]);
            #pragma unroll
            for (int ni = 0; ni < 8; ni++)
                mma16816(s[ni], qh[kk][0], qh[kk][1], qh[kk][2], qh[kk][3],
                         kl[ni][0], kl[ni][1]);
            #pragma unroll
            for (int ni = 0; ni < 8; ni++)
                mma16816(s[ni], ql[kk][0], ql[kk][1], ql[kk][2], ql[kk][3],
                         kh[ni][0], kh[ni][1]);
        }

        // ---- scale into exp2 domain + causal mask (diagonal tile only) ----
        #pragma unroll
        for (int ni = 0; ni < 8; ni++)
            #pragma unroll
            for (int r = 0; r < 4; r++) s[ni][r] *= SCL2;
        if (j == iq) {
            const int rlo = w * 16 + (lane >> 2), rhi = rlo + 8;
            #pragma unroll
            for (int ni = 0; ni < 8; ni++) {
                const int c0 = ni * 8 + (lane & 3) * 2;
                if (c0 > rlo)     s[ni][0] = -1e30f;
                if (c0 + 1 > rlo) s[ni][1] = -1e30f;
                if (c0 > rhi)     s[ni][2] = -1e30f;
                if (c0 + 1 > rhi) s[ni][3] = -1e30f;
            }
        }

        // ---- online softmax (fp32, base-2) ----
        float mx_lo = s[0][0], mx_hi = s[0][2];
        #pragma unroll
        for (int ni = 0; ni < 8; ni++) {
            mx_lo = fmaxf(mx_lo, fmaxf(s[ni][0], s[ni][1]));
            mx_hi = fmaxf(mx_hi, fmaxf(s[ni][2], s[ni][3]));
        }
        mx_lo = fmaxf(mx_lo, __shfl_xor_sync(0xffffffffu, mx_lo, 1));
        mx_lo = fmaxf(mx_lo, __shfl_xor_sync(0xffffffffu, mx_lo, 2));
        mx_hi = fmaxf(mx_hi, __shfl_xor_sync(0xffffffffu, mx_hi, 1));
        mx_hi = fmaxf(mx_hi, __shfl_xor_sync(0xffffffffu, mx_hi, 2));
        const float mn_lo = fmaxf(m_lo, mx_lo), mn_hi = fmaxf(m_hi, mx_hi);
        const float al_lo = ex2f(m_lo - mn_lo), al_hi = ex2f(m_hi - mn_hi);

        uint32_t ph[8][2], pl[8][2];
        float sum_lo = 0.f, sum_hi = 0.f;
        #pragma unroll
        for (int ni = 0; ni < 8; ni++) {
            float p0 = ex2f(s[ni][0] - mn_lo);
            float p1 = ex2f(s[ni][1] - mn_lo);
            float p2 = ex2f(s[ni][2] - mn_hi);
            float p3 = ex2f(s[ni][3] - mn_hi);
            sum_lo += p0 + p1; sum_hi += p2 + p3;
            uint32_t h01 = packbf(p0, p1), h23 = packbf(p2, p3);
            ph[ni][0] = h01; ph[ni][1] = h23;
            pl[ni][0] = packbf(p0 - bflo_f(h01), p1 - bfhi_f(h01));
            pl[ni][1] = packbf(p2 - bflo_f(h23), p3 - bfhi_f(h23));
        }
        sum_lo += __shfl_xor_sync(0xffffffffu, sum_lo, 1);
        sum_lo += __shfl_xor_sync(0xffffffffu, sum_lo, 2);
        sum_hi += __shfl_xor_sync(0xffffffffu, sum_hi, 1);
        sum_hi += __shfl_xor_sync(0xffffffffu, sum_hi, 2);
        l_lo = l_lo * al_lo + sum_lo;  m_lo = mn_lo;
        l_hi = l_hi * al_hi + sum_hi;  m_hi = mn_hi;
        #pragma unroll
        for (int ni = 0; ni < 8; ni++) {
            o[ni][0] *= al_lo; o[ni][1] *= al_lo;
            o[ni][2] *= al_hi; o[ni][3] *= al_hi;
        }

        // ---- O += P V (3-term) ----
        #pragma unroll
        for (int kk = 0; kk < 4; kk++) {
            uint32_t vh[8][2], vl[8][2];
            #pragma unroll
            for (int np = 0; np < 4; np++) {
                uint32_t t0, t1, t2, t3;
                ldsm4(stb + 2 * A_TILE * 2 + b_off + np * (16 * APAD * 2) + kk * 32, t0, t1, t2, t3);
                vh[2 * np][0] = t0; vh[2 * np][1] = t2;
                vh[2 * np + 1][0] = t1; vh[2 * np + 1][1] = t3;
                ldsm4(stb + 3 * A_TILE * 2 + b_off + np * (16 * APAD * 2) + kk * 32, t0, t1, t2, t3);
                vl[2 * np][0] = t0; vl[2 * np][1] = t2;
                vl[2 * np + 1][0] = t1; vl[2 * np + 1][1] = t3;
            }
            const uint32_t pa0 = ph[2 * kk][0], pa1 = ph[2 * kk][1];
            const uint32_t pa2 = ph[2 * kk + 1][0], pa3 = ph[2 * kk + 1][1];
            const uint32_t qa0 = pl[2 * kk][0], qa1 = pl[2 * kk][1];
            const uint32_t qa2 = pl[2 * kk + 1][0], qa3 = pl[2 * kk + 1][1];
            #pragma unroll
            for (int ni = 0; ni < 8; ni++)
                mma16816(o[ni], pa0, pa1, pa2, pa3, vh[ni][0], vh[ni][1]);
            #pragma unroll
            for (int ni = 0; ni < 8; ni++)
                mma16816(o[ni], pa0, pa1, pa2, pa3, vl[ni][0], vl[ni][1]);
            #pragma unroll
            for (int ni = 0; ni < 8; ni++)
                mma16816(o[ni], qa0, qa1, qa2, qa3, vh[ni][0], vh[ni][1]);
        }
    }

    // ---- epilogue: X[b, s, h*64+dk] as bf16 hi/lo ----
    const float inv_lo = 1.f / l_lo, inv_hi = 1.f / l_hi;
    const int b = bh >> 4, h = bh & 15;
    const int s_lo = iq * 64 + w * 16 + (lane >> 2);
    const int s_hi = s_lo + 8;
    #pragma unroll
    for (int ni = 0; ni < 8; ni++) {
        const int dk = ni * 8 + (lane & 3) * 2;
        const size_t o_lo = ((size_t)(b * Ss + s_lo)) * Dd + h * DKk + dk;
        const size_t o_hi = ((size_t)(b * Ss + s_hi)) * Dd + h * DKk + dk;
        float v0 = o[ni][0] * inv_lo, v1 = o[ni][1] * inv_lo;
        float v2 = o[ni][2] * inv_hi, v3 = o[ni][3] * inv_hi;
        uint32_t hp0 = packbf(v0, v1), hp1 = packbf(v2, v3);
        *(uint32_t*)&X[o_lo] = hp0;
        *(uint32_t*)&X[o_hi] = hp1;
        *(uint32_t*)&X[MOFF + o_lo] = packbf(v0 - bflo_f(hp0), v1 - bfhi_f(hp0));
        *(uint32_t*)&X[MOFF + o_hi] = packbf(v2 - bflo_f(hp1), v3 - bfhi_f(hp1));
    }
    #undef ISSUE_KV
}

// ---------------------------------------------------------------------------
extern "C" void kernel_launch(void* const* d_in, const int* in_sizes, int n_in,
                              void* d_out, int out_size)
{
    const float* q   = (const float*)d_in[0];
    const float* k   = (const float*)d_in[1];
    const float* v   = (const float*)d_in[2];
    // d_in[3] = causal mask (int32) — causality computed analytically
    const float* w_q = (const float*)d_in[4];
    const float* b_q = (const float*)d_in[5];
    const float* w_k = (const float*)d_in[6];
    const float* b_k = (const float*)d_in[7];
    const float* w_v = (const float*)d_in[8];
    const float* b_v = (const float*)d_in[9];
    const float* w_o = (const float*)d_in[10];
    const float* b_o = (const float*)d_in[11];
    float* out = (float*)d_out;

    __nv_bfloat16 *pQ, *pK, *pVt, *pX;
    cudaGetSymbolAddress((void**)&pQ,  g_Q);
    cudaGetSymbolAddress((void**)&pK,  g_K);
    cudaGetSymbolAddress((void**)&pVt, g_Vt);
    cudaGetSymbolAddress((void**)&pX,  g_X);

    cudaFuncSetAttribute(hgemm_qkv,
                         cudaFuncAttributeMaxDynamicSharedMemorySize, GSMEM);
    cudaFuncSetAttribute(hgemm_out,
                         cudaFuncAttributeMaxDynamicSharedMemorySize, GSMEM);
    cudaFuncSetAttribute(attn_mma_kernel,
                         cudaFuncAttributeMaxDynamicSharedMemorySize, ATTN_SMEM);

    // conversions (weights + activations)
    dim3 wt_grid(32, 32, 4), wt_block(32, 8);
    conv_wt_all<<<wt_grid, wt_block>>>(w_q, w_k, w_v, w_o);
    dim3 ca_grid(4096, 3);
    conv_act_all<<<ca_grid, 256>>>(q, k, v);

    // batched QKV projections (128x128 tiles, 2 CTAs/SM)
    dim3 gemm_grid(Dd / 128, Mm / 128, 3);             // (8, 32, 3)
    hgemm_qkv<<<gemm_grid, 256, GSMEM>>>(b_q, b_k, b_v);

    // attention
    dim3 agrid(Ss / 64, Bb * Hh);                      // (32, 32)
    attn_mma_kernel<<<agrid, 128, ATTN_SMEM>>>(pQ, pK, pVt, pX);

    // output projection
    dim3 gemm_grid1(Dd / 128, Mm / 128, 1);            // (8, 32)
    hgemm_out<<<gemm_grid1, 256, GSMEM>>>(b_o, out);
}

// round 15
// speedup vs baseline: 1.0822x; 1.0282x over previous
#include <cuda_runtime.h>
#include <cuda_bf16.h>
#include <cstdint>

#define Bb  2
#define Ss  2048
#define Dd  1024
#define Hh  16
#define DKk 64
#define Mm  (Bb*Ss)

#define MOFF  ((size_t)Mm * Dd)        // 4194304 elems: lo-offset for activations
#define WOFF2 ((size_t)Dd * Dd)        // 1048576 elems: lo-offset for weights

// ---------------- scratch (allocation-free: device globals) ----------------
// each array: [hi | lo] halves at +0 / +offset
__device__ __nv_bfloat16 g_A0[2 * MOFF];
__device__ __nv_bfloat16 g_A1[2 * MOFF];
__device__ __nv_bfloat16 g_A2[2 * MOFF];
__device__ __nv_bfloat16 g_W0[2 * WOFF2];
__device__ __nv_bfloat16 g_W1[2 * WOFF2];
__device__ __nv_bfloat16 g_W2[2 * WOFF2];
__device__ __nv_bfloat16 g_W3[2 * WOFF2];
__device__ __nv_bfloat16 g_Q[2 * MOFF];    // [B,H,S,DK]
__device__ __nv_bfloat16 g_K[2 * MOFF];    // [B,H,S,DK]
__device__ __nv_bfloat16 g_Vt[2 * MOFF];   // [B,H,DK,S]
__device__ __nv_bfloat16 g_X[2 * MOFF];    // [B,S,D]

// ---------------- helpers (arch-portable PTX) --------
__device__ __forceinline__ uint32_t smem_u32(const void* p) {
    uint32_t a;
    asm("{ .reg .u64 t; cvta.to.shared.u64 t, %1; cvt.u32.u64 %0, t; }"
        : "=r"(a) : "l"(p));
    return a;
}
__device__ __forceinline__ void ldsm4(uint32_t a, uint32_t& r0, uint32_t& r1,
                                      uint32_t& r2, uint32_t& r3) {
    asm volatile("ldmatrix.sync.aligned.m8n8.x4.shared.b16 {%0,%1,%2,%3}, [%4];"
                 : "=r"(r0), "=r"(r1), "=r"(r2), "=r"(r3) : "r"(a));
}
__device__ __forceinline__ void mma16816(float* c, uint32_t a0, uint32_t a1,
                                         uint32_t a2, uint32_t a3,
                                         uint32_t b0, uint32_t b1) {
    asm volatile(
        "mma.sync.aligned.m16n8k16.row.col.f32.bf16.bf16.f32 "
        "{%0,%1,%2,%3}, {%4,%5,%6,%7}, {%8,%9}, {%0,%1,%2,%3};"
        : "+f"(c[0]), "+f"(c[1]), "+f"(c[2]), "+f"(c[3])
        : "r"(a0), "r"(a1), "r"(a2), "r"(a3), "r"(b0), "r"(b1));
}
__device__ __forceinline__ uint32_t packbf(float lo, float hi) {
    uint32_t r;
    asm("cvt.rn.bf16x2.f32 %0, %1, %2;" : "=r"(r) : "f"(hi), "f"(lo));
    return r;
}
__device__ __forceinline__ float bflo_f(uint32_t p) { return __uint_as_float(p << 16); }
__device__ __forceinline__ float bfhi_f(uint32_t p) { return __uint_as_float(p & 0xffff0000u); }
__device__ __forceinline__ float ex2f(float x) {
    float r;
    asm("ex2.approx.f32 %0, %1;" : "=f"(r) : "f"(x));
    return r;
}

__device__ __forceinline__ void cpasync16(uint32_t saddr, const void* g) {
    asm volatile("cp.async.ca.shared.global [%0], [%1], 16;"
                 :: "r"(saddr), "l"(g) : "memory");
}
#define CP_COMMIT() asm volatile("cp.async.commit_group;" ::: "memory")
#define CP_WAIT0()  asm volatile("cp.async.wait_group 0;" ::: "memory")

// ---------------------------------------------------------------------------
// merged fp32 -> bf16 hi/lo splits for q,k,v activations
// ---------------------------------------------------------------------------
__global__ __launch_bounds__(256) void conv_act_all(
    const float* __restrict__ q, const float* __restrict__ k,
    const float* __restrict__ v)
{
    const float* src = (blockIdx.y == 0) ? q : (blockIdx.y == 1) ? k : v;
    __nv_bfloat16* dst = (blockIdx.y == 0) ? g_A0 : (blockIdx.y == 1) ? g_A1 : g_A2;
    int i = blockIdx.x * blockDim.x + threadIdx.x;
    float4 vv = ((const float4*)src)[i];
    uint32_t h0 = packbf(vv.x, vv.y), h1 = packbf(vv.z, vv.w);
    ((uint32_t*)dst)[i * 2 + 0] = h0;
    ((uint32_t*)dst)[i * 2 + 1] = h1;
    ((uint32_t*)(dst + MOFF))[i * 2 + 0] = packbf(vv.x - bflo_f(h0), vv.y - bfhi_f(h0));
    ((uint32_t*)(dst + MOFF))[i * 2 + 1] = packbf(vv.z - bflo_f(h1), vv.w - bfhi_f(h1));
}

// ---------------------------------------------------------------------------
// merged weight transpose + split: W[K,N] -> WT[N,K] hi/lo, 4 weights
// ---------------------------------------------------------------------------
__global__ __launch_bounds__(256) void conv_wt_all(
    const float* __restrict__ w0, const float* __restrict__ w1,
    const float* __restrict__ w2, const float* __restrict__ w3)
{
    __shared__ float ts[32][33];
    const int z = blockIdx.z;
    const float* W = (z == 0) ? w0 : (z == 1) ? w1 : (z == 2) ? w2 : w3;
    __nv_bfloat16* dst = (z == 0) ? g_W0 : (z == 1) ? g_W1 : (z == 2) ? g_W2 : g_W3;
    int tx = threadIdx.x, ty = threadIdx.y;          // 32 x 8
    int bn = blockIdx.x * 32, bk = blockIdx.y * 32;
    #pragma unroll
    for (int r = 0; r < 4; r++)
        ts[ty + r * 8][tx] = W[(size_t)(bk + ty + r * 8) * Dd + bn + tx];
    __syncthreads();
    #pragma unroll
    for (int r = 0; r < 4; r++) {
        float x = ts[tx][ty + r * 8];
        __nv_bfloat16 h = __float2bfloat16(x);
        size_t o = (size_t)(bn + ty + r * 8) * Dd + bk + tx;
        dst[o] = h;
        dst[WOFF2 + o] = __float2bfloat16(x - __bfloat162float(h));
    }
}

// ---------------------------------------------------------------------------
// HMMA bf16x3 GEMM body: cp.async double-buffered, 2 CTAs/SM. (R10 config)
// CTA 128x128, K-chunk 32, 8 warps (2m x 4n), warp tile 64x32.
// Fragment reuse across the 3 passes: 12 ldsm4/ks.
// A = [hi|lo@+MOFF]; W = [hi|lo@+WOFF2]; C (mode 1/2) = [hi|lo@+MOFF].
// mode 0: fp32 row-major; 1: bf16 [B,H,S,DK]; 2: bf16 [B,H,DK,S].
// ---------------------------------------------------------------------------
#define KCH   32
#define NCHUNK (Dd / KCH)          // 32
#define SROW  40                   // padded halves per row
#define ABYTES (128 * SROW * 2)    // 10240 B per array
#define BUFB  (4 * ABYTES)         // 40960 B per stage
#define GSMEM (2 * BUFB)           // 81920 B

__device__ __forceinline__ void hgemm_body(
    const __nv_bfloat16* __restrict__ A, const __nv_bfloat16* __restrict__ W,
    const float* __restrict__ bias, float* __restrict__ Cf,
    __nv_bfloat16* __restrict__ Cb, int mode, __nv_bfloat16* sm)
{
    const int tid  = threadIdx.x;
    const int wid  = tid >> 5, lane = tid & 31;
    const int bm   = blockIdx.y * 128, bn = blockIdx.x * 128;
    const int wm   = wid & 1, wn = wid >> 1;

    float c[4][4][4];
    #pragma unroll
    for (int i = 0; i < 4; i++)
        #pragma unroll
        for (int j = 0; j < 4; j++)
            #pragma unroll
            for (int r = 0; r < 4; r++) c[i][j][r] = 0.f;

    const int r0 = tid >> 2,         q0 = (tid & 3) * 8;
    const int r1 = (tid + 256) >> 2, q1 = ((tid + 256) & 3) * 8;
    const uint32_t sb = smem_u32(sm);

    #define ISSUE_CHUNK(cc, base) do {                                          \
        const int k0_ = (cc) * KCH;                                             \
        const __nv_bfloat16* a0_ = &A[(size_t)(bm + r0) * Dd + k0_ + q0];       \
        const __nv_bfloat16* a1_ = &A[(size_t)(bm + r1) * Dd + k0_ + q1];       \
        const __nv_bfloat16* w0_ = &W[(size_t)(bn + r0) * Dd + k0_ + q0];       \
        const __nv_bfloat16* w1_ = &W[(size_t)(bn + r1) * Dd + k0_ + q1];       \
        cpasync16((base) + (uint32_t)((0 * 128 * SROW + r0 * SROW + q0) * 2), a0_);         \
        cpasync16((base) + (uint32_t)((0 * 128 * SROW + r1 * SROW + q1) * 2), a1_);         \
        cpasync16((base) + (uint32_t)((1 * 128 * SROW + r0 * SROW + q0) * 2), a0_ + MOFF);  \
        cpasync16((base) + (uint32_t)((1 * 128 * SROW + r1 * SROW + q1) * 2), a1_ + MOFF);  \
        cpasync16((base) + (uint32_t)((2 * 128 * SROW + r0 * SROW + q0) * 2), w0_);         \
        cpasync16((base) + (uint32_t)((2 * 128 * SROW + r1 * SROW + q1) * 2), w1_);         \
        cpasync16((base) + (uint32_t)((3 * 128 * SROW + r0 * SROW + q0) * 2), w0_ + WOFF2); \
        cpasync16((base) + (uint32_t)((3 * 128 * SROW + r1 * SROW + q1) * 2), w1_ + WOFF2); \
        CP_COMMIT();                                                            \
    } while (0)

    const uint32_t aoff =
        (uint32_t)(((wm * 64 + (lane & 15)) * SROW + (lane >> 4) * 8) * 2);
    // B ldsm4: lanes 0-7 -> (n0,k0), 8-15 -> (n0,k8), 16-23 -> (n1,k0), 24-31 -> (n1,k8)
    const uint32_t boff4 =
        (uint32_t)(((wn * 32 + (lane >> 4) * 8 + (lane & 7)) * SROW
                    + ((lane >> 3) & 1) * 8) * 2);

    ISSUE_CHUNK(0, sb);

    for (int cc = 0; cc < NCHUNK; cc++) {
        CP_WAIT0();
        __syncthreads();
        if (cc + 1 < NCHUNK)
            ISSUE_CHUNK(cc + 1, sb + (uint32_t)((cc + 1) & 1) * BUFB);

        const uint32_t bufb = sb + (uint32_t)(cc & 1) * BUFB;
        #pragma unroll
        for (int ks = 0; ks < 2; ks++) {
            uint32_t ah[4][4], bh[4][2], bl[4][2];
            #pragma unroll
            for (int mi = 0; mi < 4; mi++)
                ldsm4(bufb + aoff + mi * (16 * SROW * 2) + ks * 32,
                      ah[mi][0], ah[mi][1], ah[mi][2], ah[mi][3]);
            #pragma unroll
            for (int nb = 0; nb < 2; nb++)
                ldsm4(bufb + 2u * ABYTES + boff4 + nb * (16 * SROW * 2) + ks * 32,
                      bh[2 * nb][0], bh[2 * nb][1], bh[2 * nb + 1][0], bh[2 * nb + 1][1]);
            #pragma unroll
            for (int nb = 0; nb < 2; nb++)
                ldsm4(bufb + 3u * ABYTES + boff4 + nb * (16 * SROW * 2) + ks * 32,
                      bl[2 * nb][0], bl[2 * nb][1], bl[2 * nb + 1][0], bl[2 * nb + 1][1]);
            // pass 0: Ah * Bh
            #pragma unroll
            for (int mi = 0; mi < 4; mi++)
                #pragma unroll
                for (int ni = 0; ni < 4; ni++)
                    mma16816(c[mi][ni], ah[mi][0], ah[mi][1], ah[mi][2], ah[mi][3],
                             bh[ni][0], bh[ni][1]);
            // pass 1: Ah * Bl
            #pragma unroll
            for (int mi = 0; mi < 4; mi++)
                #pragma unroll
                for (int ni = 0; ni < 4; ni++)
                    mma16816(c[mi][ni], ah[mi][0], ah[mi][1], ah[mi][2], ah[mi][3],
                             bl[ni][0], bl[ni][1]);
            // A-lo fragments (overwrite ah)
            #pragma unroll
            for (int mi = 0; mi < 4; mi++)
                ldsm4(bufb + (uint32_t)ABYTES + aoff + mi * (16 * SROW * 2) + ks * 32,
                      ah[mi][0], ah[mi][1], ah[mi][2], ah[mi][3]);
            // pass 2: Al * Bh
            #pragma unroll
            for (int mi = 0; mi < 4; mi++)
                #pragma unroll
                for (int ni = 0; ni < 4; ni++)
                    mma16816(c[mi][ni], ah[mi][0], ah[mi][1], ah[mi][2], ah[mi][3],
                             bh[ni][0], bh[ni][1]);
        }
    }

    // ---- epilogue ----
    const int mrow0 = bm + wm * 64 + (lane >> 2);
    const int ncol0 = bn + wn * 32 + (lane & 3) * 2;
    #pragma unroll
    for (int mi = 0; mi < 4; mi++) {
        #pragma unroll
        for (int h2 = 0; h2 < 2; h2++) {
            const int m = mrow0 + mi * 16 + h2 * 8;
            const int b = m >> 11, s = m & 2047;
            #pragma unroll
            for (int ni = 0; ni < 4; ni++) {
                const int n = ncol0 + ni * 8;
                float v0 = c[mi][ni][h2 * 2 + 0] + bias[n];
                float v1 = c[mi][ni][h2 * 2 + 1] + bias[n + 1];
                if (mode == 0) {
                    float2 v; v.x = v0; v.y = v1;
                    *(float2*)&Cf[(size_t)m * Dd + n] = v;
                } else {
                    const int h = n >> 6, dk = n & 63;
                    uint32_t hp = packbf(v0, v1);
                    uint32_t lp = packbf(v0 - bflo_f(hp), v1 - bfhi_f(hp));
                    if (mode == 1) {
                        size_t o = (((size_t)(b * Hh + h)) * Ss + s) * DKk + dk;
                        *(uint32_t*)&Cb[o] = hp;
                        *(uint32_t*)&Cb[MOFF + o] = lp;
                    } else {
                        size_t o = (((size_t)(b * Hh + h)) * DKk + dk) * Ss + s;
                        Cb[o]      = __ushort_as_bfloat16((uint16_t)(hp & 0xffff));
                        Cb[o + Ss] = __ushort_as_bfloat16((uint16_t)(hp >> 16));
                        Cb[MOFF + o]      = __ushort_as_bfloat16((uint16_t)(lp & 0xffff));
                        Cb[MOFF + o + Ss] = __ushort_as_bfloat16((uint16_t)(lp >> 16));
                    }
                }
            }
        }
    }
    #undef ISSUE_CHUNK
}

// batched QKV projections: blockIdx.z selects {Q, K, V}
__global__ __launch_bounds__(256, 2) void hgemm_qkv(
    const float* __restrict__ b_q, const float* __restrict__ b_k,
    const float* __restrict__ b_v)
{
    extern __shared__ __nv_bfloat16 smg[];
    const int z = blockIdx.z;
    if (z == 0)
        hgemm_body(g_A0, g_W0, b_q, nullptr, g_Q, 1, smg);
    else if (z == 1)
        hgemm_body(g_A1, g_W1, b_k, nullptr, g_K, 1, smg);
    else
        hgemm_body(g_A2, g_W2, b_v, nullptr, g_Vt, 2, smg);
}

__global__ __launch_bounds__(256, 2) void hgemm_out(
    const float* __restrict__ b_o, float* __restrict__ out)
{
    extern __shared__ __nv_bfloat16 smg[];
    hgemm_body(g_X, g_W3, b_o, out, nullptr, 0, smg);
}

// ---------------------------------------------------------------------------
// HMMA flash attention, bf16x3, causal, cp.async double-buffered KV.
// CTA: 64 query rows of one (b,h); 4 warps x 16 rows. KV tiles of 64 keys.
// (R10 form; merged hi/lo pointers, .ca policy)
// ---------------------------------------------------------------------------
#define APAD 72
#define A_TILE (64 * APAD)             // 4608 halves = 9216 B
#define STAGE_H (4 * A_TILE)           // KH,KL,VH,VL per stage
#define ATTN_SMEM ((2 * A_TILE + 2 * STAGE_H) * 2)   // 92160 B
#define SCL2 0.18033688f               // 0.125 * log2(e)

__global__ __launch_bounds__(128, 1) void attn_mma_kernel(
    const __nv_bfloat16* __restrict__ Q, const __nv_bfloat16* __restrict__ K,
    const __nv_bfloat16* __restrict__ Vt, __nv_bfloat16* __restrict__ X)
{
    extern __shared__ __nv_bfloat16 smA[];
    const int tid  = threadIdx.x;
    const int w    = tid >> 5, lane = tid & 31;
    const int bh   = blockIdx.y;
    const int iq   = gridDim.x - 1 - blockIdx.x;   // long CTAs first
    const size_t baseQK = (size_t)bh * Ss * DKk;
    const size_t baseV  = (size_t)bh * DKk * Ss;
    const uint32_t sb = smem_u32(smA);

    #define ISSUE_KV(j, stg) do {                                               \
        const __nv_bfloat16* Kg_ = K + baseQK + (size_t)(j) * 64 * DKk;         \
        const __nv_bfloat16* Vg_ = Vt + baseV + (size_t)(j) * 64;               \
        const uint32_t st = sb + (uint32_t)((2 * A_TILE + (stg) * STAGE_H) * 2);\
        _Pragma("unroll")                                                       \
        for (int t = 0; t < 4; t++) {                                           \
            int idx = tid + t * 128;                                            \
            int row = idx >> 3, cu = (idx & 7) * 8;                             \
            cpasync16(st + (uint32_t)((0 * A_TILE + row * APAD + cu) * 2),      \
                      Kg_ + row * DKk + cu);                                    \
            cpasync16(st + (uint32_t)((1 * A_TILE + row * APAD + cu) * 2),      \
                      Kg_ + MOFF + row * DKk + cu);                             \
            cpasync16(st + (uint32_t)((2 * A_TILE + row * APAD + cu) * 2),      \
                      Vg_ + (size_t)row * Ss + cu);                             \
            cpasync16(st + (uint32_t)((3 * A_TILE + row * APAD + cu) * 2),      \
                      Vg_ + MOFF + (size_t)row * Ss + cu);                      \
        }                                                                       \
        CP_COMMIT();                                                            \
    } while (0)

    // ---- load Q tile (64x64 hi/lo) + prefetch KV tile 0 ----
    {
        const __nv_bfloat16* Qg_ = Q + baseQK + (size_t)iq * 64 * DKk;
        #pragma unroll
        for (int t = 0; t < 4; t++) {
            int idx = tid + t * 128;
            int row = idx >> 3, cu = (idx & 7) * 8;
            *(uint4*)&smA[0 * A_TILE + row * APAD + cu] =
                *(const uint4*)(Qg_ + row * DKk + cu);
            *(uint4*)&smA[1 * A_TILE + row * APAD + cu] =
                *(const uint4*)(Qg_ + MOFF + row * DKk + cu);
        }
    }
    ISSUE_KV(0, 0);
    __syncthreads();

    const uint32_t a_off = (uint32_t)(((w * 16 + (lane & 15)) * APAD + (lane >> 4) * 8) * 2);
    const uint32_t b_off = (uint32_t)((((lane & 15)) * APAD + (lane >> 4) * 8) * 2);

    uint32_t qh[4][4], ql[4][4];
    #pragma unroll
    for (int kk = 0; kk < 4; kk++) {
        ldsm4(sb + 0 * A_TILE * 2 + a_off + kk * 32, qh[kk][0], qh[kk][1], qh[kk][2], qh[kk][3]);
        ldsm4(sb + 1 * A_TILE * 2 + a_off + kk * 32, ql[kk][0], ql[kk][1], ql[kk][2], ql[kk][3]);
    }

    float o[8][4];
    #pragma unroll
    for (int i = 0; i < 8; i++)
        #pragma unroll
        for (int r = 0; r < 4; r++) o[i][r] = 0.f;
    float m_lo = -1e30f, m_hi = -1e30f, l_lo = 0.f, l_hi = 0.f;

    for (int j = 0; j <= iq; j++) {
        CP_WAIT0();
        __syncthreads();
        if (j < iq) ISSUE_KV(j + 1, (j + 1) & 1);

        const uint32_t stb = sb + (uint32_t)((2 * A_TILE + (j & 1) * STAGE_H) * 2);

        // ---- scores S = Q K^T (3-term) ----
        float s[8][4];
        #pragma unroll
        for (int i = 0; i < 8; i++)
            #pragma unroll
            for (int r = 0; r < 4; r++) s[i][r] = 0.f;

        #pragma unroll
        for (int kk = 0; kk < 4; kk++) {
            uint32_t kh[8][2], kl[8][2];
            #pragma unroll
            for (int np = 0; np < 4; np++) {
                uint32_t t0, t1, t2, t3;
                ldsm4(stb + 0 * A_TILE * 2 + b_off + np * (16 * APAD * 2) + kk * 32, t0, t1, t2, t3);
                kh[2 * np][0] = t0; kh[2 * np][1] = t2;
                kh[2 * np + 1][0] = t1; kh[2 * np + 1][1] = t3;
                ldsm4(stb + 1 * A_TILE * 2 + b_off + np * (16 * APAD * 2) + kk * 32, t0, t1, t2, t3);
                kl[2 * np][0] = t0; kl[2 * np][1] = t2;
                kl[2 * np + 1][0] = t1; kl[2 * np + 1][1] = t3;
            }
            #pragma unroll
            for (int ni = 0; ni < 8; ni++)
                mma16816(s[ni], qh[kk][0], qh[kk][1], qh[kk][2], qh[kk][3],
                         kh[ni][0], kh[ni][1]);
            #pragma unroll
            for (int ni = 0; ni < 8; ni++)
                mma16816(s[ni], qh[kk][0], qh[kk][1], qh[kk][2], qh[kk][3],
                         kl[ni][0], kl[ni][1]);
            #pragma unroll
            for (int ni = 0; ni < 8; ni++)
                mma16816(s[ni], ql[kk][0], ql[kk][1], ql[kk][2], ql[kk][3],
                         kh[ni][0], kh[ni][1]);
        }

        // ---- scale into exp2 domain + causal mask (diagonal tile only) ----
        #pragma unroll
        for (int ni = 0; ni < 8; ni++)
            #pragma unroll
            for (int r = 0; r < 4; r++) s[ni][r] *= SCL2;
        if (j == iq) {
            const int rlo = w * 16 + (lane >> 2), rhi = rlo + 8;
            #pragma unroll
            for (int ni = 0; ni < 8; ni++) {
                const int c0 = ni * 8 + (lane & 3) * 2;
                if (c0 > rlo)     s[ni][0] = -1e30f;
                if (c0 + 1 > rlo) s[ni][1] = -1e30f;
                if (c0 > rhi)     s[ni][2] = -1e30f;
                if (c0 + 1 > rhi) s[ni][3] = -1e30f;
            }
        }

        // ---- online softmax (fp32, base-2) ----
        float mx_lo = s[0][0], mx_hi = s[0][2];
        #pragma unroll
        for (int ni = 0; ni < 8; ni++) {
            mx_lo = fmaxf(mx_lo, fmaxf(s[ni][0], s[ni][1]));
            mx_hi = fmaxf(mx_hi, fmaxf(s[ni][2], s[ni][3]));
        }
        mx_lo = fmaxf(mx_lo, __shfl_xor_sync(0xffffffffu, mx_lo, 1));
        mx_lo = fmaxf(mx_lo, __shfl_xor_sync(0xffffffffu, mx_lo, 2));
        mx_hi = fmaxf(mx_hi, __shfl_xor_sync(0xffffffffu, mx_hi, 1));
        mx_hi = fmaxf(mx_hi, __shfl_xor_sync(0xffffffffu, mx_hi, 2));
        const float mn_lo = fmaxf(m_lo, mx_lo), mn_hi = fmaxf(m_hi, mx_hi);
        const float al_lo = ex2f(m_lo - mn_lo), al_hi = ex2f(m_hi - mn_hi);

        uint32_t ph[8][2], pl[8][2];
        float sum_lo = 0.f, sum_hi = 0.f;
        #pragma unroll
        for (int ni = 0; ni < 8; ni++) {
            float p0 = ex2f(s[ni][0] - mn_lo);
            float p1 = ex2f(s[ni][1] - mn_lo);
            float p2 = ex2f(s[ni][2] - mn_hi);
            float p3 = ex2f(s[ni][3] - mn_hi);
            sum_lo += p0 + p1; sum_hi += p2 + p3;
            uint32_t h01 = packbf(p0, p1), h23 = packbf(p2, p3);
            ph[ni][0] = h01; ph[ni][1] = h23;
            pl[ni][0] = packbf(p0 - bflo_f(h01), p1 - bfhi_f(h01));
            pl[ni][1] = packbf(p2 - bflo_f(h23), p3 - bfhi_f(h23));
        }
        sum_lo += __shfl_xor_sync(0xffffffffu, sum_lo, 1);
        sum_lo += __shfl_xor_sync(0xffffffffu, sum_lo, 2);
        sum_hi += __shfl_xor_sync(0xffffffffu, sum_hi, 1);
        sum_hi += __shfl_xor_sync(0xffffffffu, sum_hi, 2);
        l_lo = l_lo * al_lo + sum_lo;  m_lo = mn_lo;
        l_hi = l_hi * al_hi + sum_hi;  m_hi = mn_hi;
        #pragma unroll
        for (int ni = 0; ni < 8; ni++) {
            o[ni][0] *= al_lo; o[ni][1] *= al_lo;
            o[ni][2] *= al_hi; o[ni][3] *= al_hi;
        }

        // ---- O += P V (3-term) ----
        #pragma unroll
        for (int kk = 0; kk < 4; kk++) {
            uint32_t vh[8][2], vl[8][2];
            #pragma unroll
            for (int np = 0; np < 4; np++) {
                uint32_t t0, t1, t2, t3;
                ldsm4(stb + 2 * A_TILE * 2 + b_off + np * (16 * APAD * 2) + kk * 32, t0, t1, t2, t3);
                vh[2 * np][0] = t0; vh[2 * np][1] = t2;
                vh[2 * np + 1][0] = t1; vh[2 * np + 1][1] = t3;
                ldsm4(stb + 3 * A_TILE * 2 + b_off + np * (16 * APAD * 2) + kk * 32, t0, t1, t2, t3);
                vl[2 * np][0] = t0; vl[2 * np][1] = t2;
                vl[2 * np + 1][0] = t1; vl[2 * np + 1][1] = t3;
            }
            const uint32_t pa0 = ph[2 * kk][0], pa1 = ph[2 * kk][1];
            const uint32_t pa2 = ph[2 * kk + 1][0], pa3 = ph[2 * kk + 1][1];
            const uint32_t qa0 = pl[2 * kk][0], qa1 = pl[2 * kk][1];
            const uint32_t qa2 = pl[2 * kk + 1][0], qa3 = pl[2 * kk + 1][1];
            #pragma unroll
            for (int ni = 0; ni < 8; ni++)
                mma16816(o[ni], pa0, pa1, pa2, pa3, vh[ni][0], vh[ni][1]);
            #pragma unroll
            for (int ni = 0; ni < 8; ni++)
                mma16816(o[ni], pa0, pa1, pa2, pa3, vl[ni][0], vl[ni][1]);
            #pragma unroll
            for (int ni = 0; ni < 8; ni++)
                mma16816(o[ni], qa0, qa1, qa2, qa3, vh[ni][0], vh[ni][1]);
        }
    }

    // ---- epilogue: X[b, s, h*64+dk] as bf16 hi/lo ----
    const float inv_lo = 1.f / l_lo, inv_hi = 1.f / l_hi;
    const int b = bh >> 4, h = bh & 15;
    const int s_lo = iq * 64 + w * 16 + (lane >> 2);
    const int s_hi = s_lo + 8;
    #pragma unroll
    for (int ni = 0; ni < 8; ni++) {
        const int dk = ni * 8 + (lane & 3) * 2;
        const size_t o_lo = ((size_t)(b * Ss + s_lo)) * Dd + h * DKk + dk;
        const size_t o_hi = ((size_t)(b * Ss + s_hi)) * Dd + h * DKk + dk;
        float v0 = o[ni][0] * inv_lo, v1 = o[ni][1] * inv_lo;
        float v2 = o[ni][2] * inv_hi, v3 = o[ni][3] * inv_hi;
        uint32_t hp0 = packbf(v0, v1), hp1 = packbf(v2, v3);
        *(uint32_t*)&X[o_lo] = hp0;
        *(uint32_t*)&X[o_hi] = hp1;
        *(uint32_t*)&X[MOFF + o_lo] = packbf(v0 - bflo_f(hp0), v1 - bfhi_f(hp0));
        *(uint32_t*)&X[MOFF + o_hi] = packbf(v2 - bflo_f(hp1), v3 - bfhi_f(hp1));
    }
    #undef ISSUE_KV
}

// ---------------------------------------------------------------------------
extern "C" void kernel_launch(void* const* d_in, const int* in_sizes, int n_in,
                              void* d_out, int out_size)
{
    const float* q   = (const float*)d_in[0];
    const float* k   = (const float*)d_in[1];
    const float* v   = (const float*)d_in[2];
    // d_in[3] = causal mask (int32) — causality computed analytically
    const float* w_q = (const float*)d_in[4];
    const float* b_q = (const float*)d_in[5];
    const float* w_k = (const float*)d_in[6];
    const float* b_k = (const float*)d_in[7];
    const float* w_v = (const float*)d_in[8];
    const float* b_v = (const float*)d_in[9];
    const float* w_o = (const float*)d_in[10];
    const float* b_o = (const float*)d_in[11];
    float* out = (float*)d_out;

    __nv_bfloat16 *pQ, *pK, *pVt, *pX;
    cudaGetSymbolAddress((void**)&pQ,  g_Q);
    cudaGetSymbolAddress((void**)&pK,  g_K);
    cudaGetSymbolAddress((void**)&pVt, g_Vt);
    cudaGetSymbolAddress((void**)&pX,  g_X);

    cudaFuncSetAttribute(hgemm_qkv,
                         cudaFuncAttributeMaxDynamicSharedMemorySize, GSMEM);
    cudaFuncSetAttribute(hgemm_out,
                         cudaFuncAttributeMaxDynamicSharedMemorySize, GSMEM);
    cudaFuncSetAttribute(attn_mma_kernel,
                         cudaFuncAttributeMaxDynamicSharedMemorySize, ATTN_SMEM);

    // conversions (weights + activations)
    dim3 wt_grid(32, 32, 4), wt_block(32, 8);
    conv_wt_all<<<wt_grid, wt_block>>>(w_q, w_k, w_v, w_o);
    dim3 ca_grid(4096, 3);
    conv_act_all<<<ca_grid, 256>>>(q, k, v);

    // batched QKV projections (128x128 tiles, 2 CTAs/SM)
    dim3 gemm_grid(Dd / 128, Mm / 128, 3);             // (8, 32, 3)
    hgemm_qkv<<<gemm_grid, 256, GSMEM>>>(b_q, b_k, b_v);

    // attention
    dim3 agrid(Ss / 64, Bb * Hh);                      // (32, 32)
    attn_mma_kernel<<<agrid, 128, ATTN_SMEM>>>(pQ, pK, pVt, pX);

    // output projection
    dim3 gemm_grid1(Dd / 128, Mm / 128, 1);            // (8, 32)
    hgemm_out<<<gemm_grid1, 256, GSMEM>>>(b_o, out);
}